// round 7
// baseline (speedup 1.0000x reference)
#include <cuda_runtime.h>

#define NN 10000
#define EE 300000

// ---------------- scratch (__device__ globals, no allocs) ----------------
__device__ __align__(16) float g_h[NN * 32];
__device__ __align__(16) float g_k2[(size_t)EE * 256];
__device__ __align__(16) float g_G[(size_t)256 * NN * 32];   // [c][n][i]
__device__ __align__(16) float g_Bias[NN * 32];
__device__ __align__(16) float g_agg[NN * 32];
__device__ __align__(16) float g_cacc[NN * 3];
__device__ __align__(16) float g_coord[NN * 3];
__device__ float g_cntf[NN];
__device__ int   g_colcnt[NN];
__device__ int   g_rowcnt[NN];
__device__ int   g_cursor[NN];
__device__ int   g_colstart[NN + 1];
__device__ int   g_perm[EE];
__device__ int   g_is64;

// ---------------- tf32 helpers ----------------
__device__ __forceinline__ float tf32r(float f) {
    unsigned r;
    asm("cvt.rna.tf32.f32 %0, %1;" : "=r"(r) : "f"(f));
    return __uint_as_float(r);
}

__device__ __forceinline__ void mma_tf32(float* c, const unsigned* a, const unsigned* b) {
    asm volatile(
        "mma.sync.aligned.m16n8k8.row.col.f32.tf32.tf32.f32 "
        "{%0,%1,%2,%3}, {%4,%5,%6,%7}, {%8,%9}, {%0,%1,%2,%3};"
        : "+f"(c[0]), "+f"(c[1]), "+f"(c[2]), "+f"(c[3])
        : "r"(a[0]), "r"(a[1]), "r"(a[2]), "r"(a[3]), "r"(b[0]), "r"(b[1]));
}

// ---------------- edge-index dtype handling ----------------
__global__ void detect_kernel(const void* __restrict__ ei) {
    const int* w = (const int*)ei;
    int lane = threadIdx.x;
    int hi = w[2 * lane + 1];
    unsigned any = __ballot_sync(0xffffffffu, hi != 0);
    if (lane == 0) g_is64 = (any == 0u) ? 1 : 0;
}

__device__ __forceinline__ int eidx(const void* __restrict__ ei, long long pos, int is64) {
    int v = is64 ? (int)((const long long*)ei)[pos] : ((const int*)ei)[pos];
    return min(max(v, 0), NN - 1);
}

// ---------------- small utility kernels ----------------
__global__ void zero_sort_kernel() {
    int i = blockIdx.x * blockDim.x + threadIdx.x;
    if (i < NN) { g_colcnt[i] = 0; g_rowcnt[i] = 0; g_cursor[i] = 0; }
}

__global__ void zero_acc_kernel() {
    int i = blockIdx.x * blockDim.x + threadIdx.x;
    if (i < NN * 32) g_agg[i] = 0.f;
    if (i < NN * 3)  g_cacc[i] = 0.f;
}

__global__ void coordinit_kernel(const float* __restrict__ ci) {
    int i = blockIdx.x * blockDim.x + threadIdx.x;
    if (i < NN * 3) g_coord[i] = ci[i];
}

__global__ void hist_kernel(const void* __restrict__ ei) {
    int e = blockIdx.x * blockDim.x + threadIdx.x;
    int is64 = g_is64;
    if (e < EE) {
        atomicAdd(&g_rowcnt[eidx(ei, e, is64)], 1);
        atomicAdd(&g_colcnt[eidx(ei, (long long)EE + e, is64)], 1);
    }
}

__global__ void cntf_kernel() {
    int n = blockIdx.x * blockDim.x + threadIdx.x;
    if (n < NN) g_cntf[n] = fmaxf(1.f, (float)g_rowcnt[n]);
}

__global__ void scan_kernel() {
    const int BPT = 10;
    int t = threadIdx.x;
    int loc[BPT];
    int s = 0;
#pragma unroll
    for (int j = 0; j < BPT; j++) {
        int b = t * BPT + j;
        int v = (b < NN) ? g_colcnt[b] : 0;
        loc[j] = s; s += v;
    }
    unsigned full = 0xffffffffu;
    int lane = t & 31, wid = t >> 5;
    int v = s;
#pragma unroll
    for (int o = 1; o < 32; o <<= 1) {
        int u = __shfl_up_sync(full, v, o);
        if (lane >= o) v += u;
    }
    __shared__ int wsum[32];
    if (lane == 31) wsum[wid] = v;
    __syncthreads();
    if (wid == 0) {
        int x = wsum[lane];
#pragma unroll
        for (int o = 1; o < 32; o <<= 1) {
            int u = __shfl_up_sync(full, x, o);
            if (lane >= o) x += u;
        }
        wsum[lane] = x;
    }
    __syncthreads();
    int excl = v - s + (wid ? wsum[wid - 1] : 0);
#pragma unroll
    for (int j = 0; j < BPT; j++) {
        int b = t * BPT + j;
        if (b < NN) g_colstart[b] = excl + loc[j];
    }
    if (t == 1023) g_colstart[NN] = wsum[31];
}

__global__ void scatter_kernel(const void* __restrict__ ei) {
    int e = blockIdx.x * blockDim.x + threadIdx.x;
    if (e < EE) {
        int c = eidx(ei, (long long)EE + e, g_is64);
        int p = atomicAdd(&g_cursor[c], 1);
        g_perm[g_colstart[c] + p] = e;
    }
}

// ---------------- model kernels ----------------
__global__ void h0_kernel(const float* __restrict__ x,
                          const float* __restrict__ w, const float* __restrict__ b) {
    int idx = blockIdx.x * blockDim.x + threadIdx.x;
    if (idx >= NN * 32) return;
    int n = idx >> 5, i = idx & 31;
    float acc = b[i];
#pragma unroll
    for (int f = 0; f < 3; f++) acc = fmaf(x[n * 3 + f], w[f * 32 + i], acc);
    g_h[idx] = acc;
}

// k2 = relu(relu(ea@W1+b1)@W2+b2), 3xTF32 mma. Tile: 32 edges x 64 cols.
__global__ void __launch_bounds__(256) k2_mma_kernel(
    const float* __restrict__ ea,
    const float* __restrict__ w1, const float* __restrict__ b1,
    const float* __restrict__ w2, const float* __restrict__ b2)
{
    __shared__ float t1f[32 * 129];
    __shared__ float As_b[32 * 36], As_s[32 * 36];
    __shared__ float w2s_b[32 * 72], w2s_s[32 * 72];

    int e0 = blockIdx.x * 32;
    int n0 = blockIdx.y * 64;
    int tid = threadIdx.x;

    // t1 fp32 (exact)
    for (int idx = tid; idx < 32 * 128; idx += 256) {
        int el = idx >> 7, j = idx & 127;
        float acc = b1[j];
#pragma unroll
        for (int f = 0; f < 6; f++) acc = fmaf(ea[(e0 + el) * 6 + f], w1[f * 128 + j], acc);
        t1f[el * 129 + j] = fmaxf(acc, 0.f);
    }

    int w = tid >> 5, lane = tid & 31;
    int g = lane >> 2, tig = lane & 3;
    int wm = w & 1, wn = w >> 1;

    float acc[2][4] = {};

#pragma unroll 1
    for (int kb = 0; kb < 4; kb++) {
        __syncthreads();
        for (int idx = tid; idx < 1024; idx += 256) {
            int el = idx >> 5, kl = idx & 31;
            float v = t1f[el * 129 + kb * 32 + kl];
            float b = tf32r(v);
            As_b[el * 36 + kl] = b;
            As_s[el * 36 + kl] = tf32r(v - b);
        }
        for (int idx = tid; idx < 2048; idx += 256) {
            int kl = idx >> 6, nl = idx & 63;
            float v = w2[(kb * 32 + kl) * 256 + n0 + nl];
            float b = tf32r(v);
            w2s_b[kl * 72 + nl] = b;
            w2s_s[kl * 72 + nl] = tf32r(v - b);
        }
        __syncthreads();
#pragma unroll
        for (int ks = 0; ks < 4; ks++) {
            int kk = ks * 8;
            unsigned ab[4], asr[4];
            int r0 = wm * 16 + g;
            ab[0]  = __float_as_uint(As_b[r0 * 36 + kk + tig]);
            ab[1]  = __float_as_uint(As_b[(r0 + 8) * 36 + kk + tig]);
            ab[2]  = __float_as_uint(As_b[r0 * 36 + kk + tig + 4]);
            ab[3]  = __float_as_uint(As_b[(r0 + 8) * 36 + kk + tig + 4]);
            asr[0] = __float_as_uint(As_s[r0 * 36 + kk + tig]);
            asr[1] = __float_as_uint(As_s[(r0 + 8) * 36 + kk + tig]);
            asr[2] = __float_as_uint(As_s[r0 * 36 + kk + tig + 4]);
            asr[3] = __float_as_uint(As_s[(r0 + 8) * 36 + kk + tig + 4]);
#pragma unroll
            for (int ni = 0; ni < 2; ni++) {
                int c0l = wn * 16 + ni * 8 + g;
                unsigned bb[2], bsr[2];
                bb[0]  = __float_as_uint(w2s_b[(kk + tig) * 72 + c0l]);
                bb[1]  = __float_as_uint(w2s_b[(kk + tig + 4) * 72 + c0l]);
                bsr[0] = __float_as_uint(w2s_s[(kk + tig) * 72 + c0l]);
                bsr[1] = __float_as_uint(w2s_s[(kk + tig + 4) * 72 + c0l]);
                mma_tf32(acc[ni], ab, bb);
                mma_tf32(acc[ni], ab, bsr);
                mma_tf32(acc[ni], asr, bb);
            }
        }
    }

    int r = wm * 16 + g;
#pragma unroll
    for (int ni = 0; ni < 2; ni++) {
        int col = n0 + wn * 16 + ni * 8 + 2 * tig;
        float bz0 = b2[col], bz1 = b2[col + 1];
        g_k2[(size_t)(e0 + r) * 256 + col]         = fmaxf(acc[ni][0] + bz0, 0.f);
        g_k2[(size_t)(e0 + r) * 256 + col + 1]     = fmaxf(acc[ni][1] + bz1, 0.f);
        g_k2[(size_t)(e0 + r + 8) * 256 + col]     = fmaxf(acc[ni][2] + bz0, 0.f);
        g_k2[(size_t)(e0 + r + 8) * 256 + col + 1] = fmaxf(acc[ni][3] + bz1, 0.f);
    }
}

// G[c][n][i] = sum_j ker3[c][i*32+j] * h[n][j], 3xTF32. Tile 64n x 64ci.
// bk stride 72 (>=64 cols + conflict-free fragment reads).
__global__ void __launch_bounds__(256) G_mma_kernel(const float* __restrict__ k3w) {
    __shared__ float hs_b[64 * 36], hs_s[64 * 36];
    __shared__ float bk_b[32 * 72], bk_s[32 * 72];

    int nn0 = blockIdx.x * 64;
    int ci0 = blockIdx.y * 64;
    int tid = threadIdx.x;

    for (int idx = tid; idx < 64 * 32; idx += 256) {
        int nl = idx >> 5, j = idx & 31;
        int n = nn0 + nl;
        float v = (n < NN) ? g_h[n * 32 + j] : 0.f;
        float b = tf32r(v);
        hs_b[nl * 36 + j] = b;
        hs_s[nl * 36 + j] = tf32r(v - b);
    }
    for (int idx = tid; idx < 32 * 64; idx += 256) {
        int cil = idx >> 5, j = idx & 31;
        int ci = ci0 + cil;
        float v = k3w[(size_t)(ci >> 5) * 1024 + (ci & 31) * 32 + j];
        float b = tf32r(v);
        bk_b[j * 72 + cil] = b;
        bk_s[j * 72 + cil] = tf32r(v - b);
    }
    __syncthreads();

    int w = tid >> 5, lane = tid & 31;
    int g = lane >> 2, tig = lane & 3;
    int wm = w & 1, wn = w >> 1;

    float acc[2][2][4] = {};

#pragma unroll
    for (int ks = 0; ks < 4; ks++) {
        int kk = ks * 8;
        unsigned ab[2][4], asr[2][4], bb[2][2], bsr[2][2];
#pragma unroll
        for (int mi = 0; mi < 2; mi++) {
            int r0 = wm * 32 + mi * 16 + g;
            ab[mi][0]  = __float_as_uint(hs_b[r0 * 36 + kk + tig]);
            ab[mi][1]  = __float_as_uint(hs_b[(r0 + 8) * 36 + kk + tig]);
            ab[mi][2]  = __float_as_uint(hs_b[r0 * 36 + kk + tig + 4]);
            ab[mi][3]  = __float_as_uint(hs_b[(r0 + 8) * 36 + kk + tig + 4]);
            asr[mi][0] = __float_as_uint(hs_s[r0 * 36 + kk + tig]);
            asr[mi][1] = __float_as_uint(hs_s[(r0 + 8) * 36 + kk + tig]);
            asr[mi][2] = __float_as_uint(hs_s[r0 * 36 + kk + tig + 4]);
            asr[mi][3] = __float_as_uint(hs_s[(r0 + 8) * 36 + kk + tig + 4]);
        }
#pragma unroll
        for (int ni = 0; ni < 2; ni++) {
            int c0l = wn * 16 + ni * 8 + g;
            bb[ni][0]  = __float_as_uint(bk_b[(kk + tig) * 72 + c0l]);
            bb[ni][1]  = __float_as_uint(bk_b[(kk + tig + 4) * 72 + c0l]);
            bsr[ni][0] = __float_as_uint(bk_s[(kk + tig) * 72 + c0l]);
            bsr[ni][1] = __float_as_uint(bk_s[(kk + tig + 4) * 72 + c0l]);
        }
#pragma unroll
        for (int mi = 0; mi < 2; mi++)
#pragma unroll
            for (int ni = 0; ni < 2; ni++) {
                mma_tf32(acc[mi][ni], ab[mi], bb[ni]);
                mma_tf32(acc[mi][ni], ab[mi], bsr[ni]);
                mma_tf32(acc[mi][ni], asr[mi], bb[ni]);
            }
    }

#pragma unroll
    for (int mi = 0; mi < 2; mi++) {
        int na = nn0 + wm * 32 + mi * 16 + g;
        int nb = na + 8;
#pragma unroll
        for (int ni = 0; ni < 2; ni++) {
            int ci = ci0 + wn * 16 + ni * 8 + 2 * tig;
            size_t o0 = (size_t)(ci >> 5) * (NN * 32) + (ci & 31);
            size_t o1 = (size_t)((ci + 1) >> 5) * (NN * 32) + ((ci + 1) & 31);
            if (na < NN) {
                g_G[o0 + (size_t)na * 32] = acc[mi][ni][0];
                g_G[o1 + (size_t)na * 32] = acc[mi][ni][1];
            }
            if (nb < NN) {
                g_G[o0 + (size_t)nb * 32] = acc[mi][ni][2];
                g_G[o1 + (size_t)nb * 32] = acc[mi][ni][3];
            }
        }
    }
}

// Bias[n][i] = sum_j ker3_b[i*32+j] * h[n][j]  (exact fp32)
__global__ void bias_kernel(const float* __restrict__ b3) {
    int idx = blockIdx.x * blockDim.x + threadIdx.x;
    if (idx >= NN * 32) return;
    int n = idx >> 5, i = idx & 31;
    float acc = 0.f;
#pragma unroll
    for (int j = 0; j < 32; j++) acc = fmaf(b3[i * 32 + j], g_h[n * 32 + j], acc);
    g_Bias[idx] = acc;
}

// Edge message pass via MMA. One block per destination node (col), groups of
// 32 edges: m[32,32] = k2[32,256] @ G_n[256,32] + Bias (3xTF32), then
// cm1 MLP also via MMA, then scattered atomics.
__global__ void __launch_bounds__(256) edge_mma_kernel(
    const void* __restrict__ ei,
    const float* __restrict__ cm1w, const float* __restrict__ cm1b,
    const float* __restrict__ cm2w, const float* __restrict__ cm2b)
{
    int n = blockIdx.x;
    int cs0 = g_colstart[n];
    int deg = g_colstart[n + 1] - cs0;
    if (deg == 0) return;

    __shared__ float Gs_b[32 * 40], Gs_s[32 * 40];
    __shared__ float As_b[32 * 36], As_s[32 * 36];
    __shared__ float ms[32 * 33], ts[32 * 33];
    __shared__ float cm1s_b[32 * 40], cm1s_s[32 * 40];
    __shared__ float Bs_sh[32], cm1bs_sh[32], cm2s_sh[32];
    __shared__ int   es_sh[32];
    __shared__ float cm2b0_sh, ccol_sh[3];

    int tid = threadIdx.x;
    int is64 = g_is64;

    for (int idx = tid; idx < 1024; idx += 256) {
        int i = idx >> 5, j = idx & 31;
        float v = cm1w[idx];
        float b = tf32r(v);
        cm1s_b[i * 40 + j] = b;
        cm1s_s[i * 40 + j] = tf32r(v - b);
    }
    if (tid < 32) {
        Bs_sh[tid] = g_Bias[n * 32 + tid];
        cm1bs_sh[tid] = cm1b[tid];
        cm2s_sh[tid] = cm2w[tid];
    }
    if (tid == 0) cm2b0_sh = cm2b[0];
    if (tid < 3) ccol_sh[tid] = g_coord[n * 3 + tid];

    int w = tid >> 5, lane = tid & 31;
    int g = lane >> 2, tig = lane & 3;
    int wm = w & 1, wn = w >> 1;
    int col2 = wn * 8 + 2 * tig;
    int r0 = wm * 16 + g;

    for (int base = 0; base < deg; base += 32) {
        __syncthreads();   // protect es/buffers from previous group
        if (tid < 32) {
            int p = base + tid;
            es_sh[tid] = (p < deg) ? g_perm[cs0 + p] : -1;
        }

        float acc[4];
        acc[0] = Bs_sh[col2]; acc[1] = Bs_sh[col2 + 1];
        acc[2] = acc[0];      acc[3] = acc[1];

#pragma unroll 1
        for (int kb = 0; kb < 8; kb++) {
            __syncthreads();
            for (int idx = tid; idx < 1024; idx += 256) {
                int cl = idx >> 5, i = idx & 31;
                float v = g_G[(size_t)(kb * 32 + cl) * (NN * 32) + n * 32 + i];
                float b = tf32r(v);
                Gs_b[cl * 40 + i] = b;
                Gs_s[cl * 40 + i] = tf32r(v - b);
            }
            for (int idx = tid; idx < 1024; idx += 256) {
                int el = idx >> 5, kl = idx & 31;
                int e = es_sh[el];
                float v = (e >= 0) ? g_k2[(size_t)e * 256 + kb * 32 + kl] : 0.f;
                float b = tf32r(v);
                As_b[el * 36 + kl] = b;
                As_s[el * 36 + kl] = tf32r(v - b);
            }
            __syncthreads();
#pragma unroll
            for (int ks = 0; ks < 4; ks++) {
                int kk = ks * 8;
                unsigned ab[4], asr[4], bb[2], bsr[2];
                ab[0]  = __float_as_uint(As_b[r0 * 36 + kk + tig]);
                ab[1]  = __float_as_uint(As_b[(r0 + 8) * 36 + kk + tig]);
                ab[2]  = __float_as_uint(As_b[r0 * 36 + kk + tig + 4]);
                ab[3]  = __float_as_uint(As_b[(r0 + 8) * 36 + kk + tig + 4]);
                asr[0] = __float_as_uint(As_s[r0 * 36 + kk + tig]);
                asr[1] = __float_as_uint(As_s[(r0 + 8) * 36 + kk + tig]);
                asr[2] = __float_as_uint(As_s[r0 * 36 + kk + tig + 4]);
                asr[3] = __float_as_uint(As_s[(r0 + 8) * 36 + kk + tig + 4]);
                int c0l = wn * 8 + g;
                bb[0]  = __float_as_uint(Gs_b[(kk + tig) * 40 + c0l]);
                bb[1]  = __float_as_uint(Gs_b[(kk + tig + 4) * 40 + c0l]);
                bsr[0] = __float_as_uint(Gs_s[(kk + tig) * 40 + c0l]);
                bsr[1] = __float_as_uint(Gs_s[(kk + tig + 4) * 40 + c0l]);
                mma_tf32(acc, ab, bb);
                mma_tf32(acc, ab, bsr);
                mma_tf32(acc, asr, bb);
            }
        }

        // stash m
        ms[r0 * 33 + col2]           = acc[0];
        ms[r0 * 33 + col2 + 1]       = acc[1];
        ms[(r0 + 8) * 33 + col2]     = acc[2];
        ms[(r0 + 8) * 33 + col2 + 1] = acc[3];
        __syncthreads();

        // agg atomics: warp w -> edges w*4 .. w*4+3
#pragma unroll
        for (int q = 0; q < 4; q++) {
            int el = w * 4 + q;
            int e = es_sh[el];
            if (e >= 0) {
                int r = eidx(ei, e, is64);
                atomicAdd(&g_agg[r * 32 + lane], ms[el * 33 + lane]);
            }
        }

        // stage m splits for cm1 GEMM (reuse As buffers)
        for (int idx = tid; idx < 1024; idx += 256) {
            int el = idx >> 5, j = idx & 31;
            float v = ms[el * 33 + j];
            float b = tf32r(v);
            As_b[el * 36 + j] = b;
            As_s[el * 36 + j] = tf32r(v - b);
        }
        __syncthreads();

        float tacc[4];
        tacc[0] = cm1bs_sh[col2]; tacc[1] = cm1bs_sh[col2 + 1];
        tacc[2] = tacc[0];        tacc[3] = tacc[1];
#pragma unroll
        for (int ks = 0; ks < 4; ks++) {
            int kk = ks * 8;
            unsigned ab[4], asr[4], bb[2], bsr[2];
            ab[0]  = __float_as_uint(As_b[r0 * 36 + kk + tig]);
            ab[1]  = __float_as_uint(As_b[(r0 + 8) * 36 + kk + tig]);
            ab[2]  = __float_as_uint(As_b[r0 * 36 + kk + tig + 4]);
            ab[3]  = __float_as_uint(As_b[(r0 + 8) * 36 + kk + tig + 4]);
            asr[0] = __float_as_uint(As_s[r0 * 36 + kk + tig]);
            asr[1] = __float_as_uint(As_s[(r0 + 8) * 36 + kk + tig]);
            asr[2] = __float_as_uint(As_s[r0 * 36 + kk + tig + 4]);
            asr[3] = __float_as_uint(As_s[(r0 + 8) * 36 + kk + tig + 4]);
            int c0l = wn * 8 + g;
            bb[0]  = __float_as_uint(cm1s_b[(kk + tig) * 40 + c0l]);
            bb[1]  = __float_as_uint(cm1s_b[(kk + tig + 4) * 40 + c0l]);
            bsr[0] = __float_as_uint(cm1s_s[(kk + tig) * 40 + c0l]);
            bsr[1] = __float_as_uint(cm1s_s[(kk + tig + 4) * 40 + c0l]);
            mma_tf32(tacc, ab, bb);
            mma_tf32(tacc, ab, bsr);
            mma_tf32(tacc, asr, bb);
        }
        ts[r0 * 33 + col2]           = fmaxf(tacc[0], 0.f) * cm2s_sh[col2];
        ts[r0 * 33 + col2 + 1]       = fmaxf(tacc[1], 0.f) * cm2s_sh[col2 + 1];
        ts[(r0 + 8) * 33 + col2]     = fmaxf(tacc[2], 0.f) * cm2s_sh[col2];
        ts[(r0 + 8) * 33 + col2 + 1] = fmaxf(tacc[3], 0.f) * cm2s_sh[col2 + 1];
        __syncthreads();

        // we = sum_j ts[e][j] + b ; coord atomics
#pragma unroll
        for (int q = 0; q < 4; q++) {
            int el = w * 4 + q;
            float v = ts[el * 33 + lane];
#pragma unroll
            for (int off = 16; off; off >>= 1) v += __shfl_xor_sync(0xffffffffu, v, off);
            int e = es_sh[el];
            if (e >= 0 && lane < 3) {
                float we = v + cm2b0_sh;
                int r = eidx(ei, e, is64);
                atomicAdd(&g_cacc[r * 3 + lane], (g_coord[r * 3 + lane] - ccol_sh[lane]) * we);
            }
        }
    }
}

__global__ void node_kernel() {
    int idx = blockIdx.x * blockDim.x + threadIdx.x;
    if (idx >= NN * 32) return;
    int n = idx >> 5, i = idx & 31;
    float cf = g_cntf[n];
    float hv = g_h[idx] + g_agg[idx] / cf;
    g_h[idx] = fmaxf(hv, 0.f);
    if (i < 3) g_coord[n * 3 + i] += g_cacc[n * 3 + i] / cf;
}

__global__ void out_kernel(const float* __restrict__ aw, const float* __restrict__ ab,
                           const float* __restrict__ bw, const float* __restrict__ bb,
                           float* __restrict__ out, int out_size) {
    int n = blockIdx.x * blockDim.x + threadIdx.x;
    if (n >= NN) return;
    float h[32];
    const float4* hp = (const float4*)(g_h + n * 32);
#pragma unroll
    for (int q = 0; q < 8; q++) {
        float4 v = hp[q];
        h[q * 4] = v.x; h[q * 4 + 1] = v.y; h[q * 4 + 2] = v.z; h[q * 4 + 3] = v.w;
    }
    float acc = bb[0];
#pragma unroll 4
    for (int j = 0; j < 64; j++) {
        float t = ab[j];
#pragma unroll
        for (int i = 0; i < 32; i++) t = fmaf(h[i], aw[i * 64 + j], t);
        acc = fmaf(fmaxf(t, 0.f), bw[j], acc);
    }
    out[n] = acc;
#pragma unroll
    for (int d = 0; d < 3; d++) {
        int idx = NN + n * 3 + d;
        if (idx < out_size) out[idx] = g_coord[n * 3 + d];
    }
}

// ---------------- launch ----------------
extern "C" void kernel_launch(void* const* d_in, const int* in_sizes, int n_in,
                              void* d_out, int out_size) {
    const float* x      = (const float*)d_in[0];
    const void*  ei     = d_in[1];
    const float* ea     = (const float*)d_in[2];
    const float* ci     = (const float*)d_in[3];
    const float* fc1w   = (const float*)d_in[4];
    const float* fc1b   = (const float*)d_in[5];
    const float* k1w    = (const float*)d_in[6];
    const float* k1b    = (const float*)d_in[7];
    const float* k2w    = (const float*)d_in[8];
    const float* k2b    = (const float*)d_in[9];
    const float* k3w    = (const float*)d_in[10];
    const float* k3b    = (const float*)d_in[11];
    const float* cm1w   = (const float*)d_in[12];
    const float* cm1b   = (const float*)d_in[13];
    const float* cm2w   = (const float*)d_in[14];
    const float* cm2b   = (const float*)d_in[15];
    const float* fc2aw  = (const float*)d_in[16];
    const float* fc2ab  = (const float*)d_in[17];
    const float* fc2bw  = (const float*)d_in[18];
    const float* fc2bb  = (const float*)d_in[19];
    float* out = (float*)d_out;

    detect_kernel<<<1, 32>>>(ei);
    zero_sort_kernel<<<(NN + 255) / 256, 256>>>();
    hist_kernel<<<(EE + 255) / 256, 256>>>(ei);
    scan_kernel<<<1, 1024>>>();
    cntf_kernel<<<(NN + 255) / 256, 256>>>();
    scatter_kernel<<<(EE + 255) / 256, 256>>>(ei);

    coordinit_kernel<<<(NN * 3 + 255) / 256, 256>>>(ci);
    h0_kernel<<<(NN * 32 + 255) / 256, 256>>>(x, fc1w, fc1b);
    k2_mma_kernel<<<dim3(EE / 32, 4), 256>>>(ea, k1w, k1b, k2w, k2b);

    for (int layer = 0; layer < 4; layer++) {
        G_mma_kernel<<<dim3((NN + 63) / 64, 128), 256>>>(k3w);
        bias_kernel<<<(NN * 32 + 255) / 256, 256>>>(k3b);
        zero_acc_kernel<<<(NN * 32 + 255) / 256, 256>>>();
        edge_mma_kernel<<<NN, 256>>>(ei, cm1w, cm1b, cm2w, cm2b);
        node_kernel<<<(NN * 32 + 255) / 256, 256>>>();
    }

    out_kernel<<<(NN + 255) / 256, 256>>>(fc2aw, fc2ab, fc2bw, fc2bb, out, out_size);
}

// round 8
// speedup vs baseline: 1.1278x; 1.1278x over previous
#include <cuda_runtime.h>

#define NN 10000
#define EE 300000

// ---------------- scratch (__device__ globals, no allocs) ----------------
__device__ __align__(16) float g_h[NN * 32];
__device__ __align__(16) float g_k2[(size_t)EE * 256];
__device__ __align__(16) float g_G2[(size_t)NN * 8192];   // [n][c*32+i] node-major
__device__ __align__(16) float g_Bias[NN * 32];
__device__ __align__(16) float g_agg[NN * 32];
__device__ __align__(16) float g_cacc[NN * 3];
__device__ __align__(16) float g_coord[NN * 3];
__device__ float g_cntf[NN];
__device__ int   g_colcnt[NN];
__device__ int   g_rowcnt[NN];
__device__ int   g_cursor[NN];
__device__ int   g_colstart[NN + 1];
__device__ int   g_perm[EE];
__device__ int   g_is64;

// ---------------- tf32 helpers ----------------
__device__ __forceinline__ float tf32r(float f) {
    unsigned r;
    asm("cvt.rna.tf32.f32 %0, %1;" : "=r"(r) : "f"(f));
    return __uint_as_float(r);
}

__device__ __forceinline__ void mma_tf32(float* c, const unsigned* a, const unsigned* b) {
    asm volatile(
        "mma.sync.aligned.m16n8k8.row.col.f32.tf32.tf32.f32 "
        "{%0,%1,%2,%3}, {%4,%5,%6,%7}, {%8,%9}, {%0,%1,%2,%3};"
        : "+f"(c[0]), "+f"(c[1]), "+f"(c[2]), "+f"(c[3])
        : "r"(a[0]), "r"(a[1]), "r"(a[2]), "r"(a[3]), "r"(b[0]), "r"(b[1]));
}

// ---------------- edge-index dtype handling ----------------
__global__ void detect_kernel(const void* __restrict__ ei) {
    const int* w = (const int*)ei;
    int lane = threadIdx.x;
    int hi = w[2 * lane + 1];
    unsigned any = __ballot_sync(0xffffffffu, hi != 0);
    if (lane == 0) g_is64 = (any == 0u) ? 1 : 0;
}

__device__ __forceinline__ int eidx(const void* __restrict__ ei, long long pos, int is64) {
    int v = is64 ? (int)((const long long*)ei)[pos] : ((const int*)ei)[pos];
    return min(max(v, 0), NN - 1);
}

// ---------------- small utility kernels ----------------
__global__ void zero_sort_kernel() {
    int i = blockIdx.x * blockDim.x + threadIdx.x;
    if (i < NN) { g_colcnt[i] = 0; g_rowcnt[i] = 0; g_cursor[i] = 0; }
}

__global__ void zero_acc_kernel() {
    int i = blockIdx.x * blockDim.x + threadIdx.x;
    if (i < NN * 32) g_agg[i] = 0.f;
    if (i < NN * 3)  g_cacc[i] = 0.f;
}

__global__ void coordinit_kernel(const float* __restrict__ ci) {
    int i = blockIdx.x * blockDim.x + threadIdx.x;
    if (i < NN * 3) g_coord[i] = ci[i];
}

__global__ void hist_kernel(const void* __restrict__ ei) {
    int e = blockIdx.x * blockDim.x + threadIdx.x;
    int is64 = g_is64;
    if (e < EE) {
        atomicAdd(&g_rowcnt[eidx(ei, e, is64)], 1);
        atomicAdd(&g_colcnt[eidx(ei, (long long)EE + e, is64)], 1);
    }
}

__global__ void cntf_kernel() {
    int n = blockIdx.x * blockDim.x + threadIdx.x;
    if (n < NN) g_cntf[n] = fmaxf(1.f, (float)g_rowcnt[n]);
}

__global__ void scan_kernel() {
    const int BPT = 10;
    int t = threadIdx.x;
    int loc[BPT];
    int s = 0;
#pragma unroll
    for (int j = 0; j < BPT; j++) {
        int b = t * BPT + j;
        int v = (b < NN) ? g_colcnt[b] : 0;
        loc[j] = s; s += v;
    }
    unsigned full = 0xffffffffu;
    int lane = t & 31, wid = t >> 5;
    int v = s;
#pragma unroll
    for (int o = 1; o < 32; o <<= 1) {
        int u = __shfl_up_sync(full, v, o);
        if (lane >= o) v += u;
    }
    __shared__ int wsum[32];
    if (lane == 31) wsum[wid] = v;
    __syncthreads();
    if (wid == 0) {
        int x = wsum[lane];
#pragma unroll
        for (int o = 1; o < 32; o <<= 1) {
            int u = __shfl_up_sync(full, x, o);
            if (lane >= o) x += u;
        }
        wsum[lane] = x;
    }
    __syncthreads();
    int excl = v - s + (wid ? wsum[wid - 1] : 0);
#pragma unroll
    for (int j = 0; j < BPT; j++) {
        int b = t * BPT + j;
        if (b < NN) g_colstart[b] = excl + loc[j];
    }
    if (t == 1023) g_colstart[NN] = wsum[31];
}

__global__ void scatter_kernel(const void* __restrict__ ei) {
    int e = blockIdx.x * blockDim.x + threadIdx.x;
    if (e < EE) {
        int c = eidx(ei, (long long)EE + e, g_is64);
        int p = atomicAdd(&g_cursor[c], 1);
        g_perm[g_colstart[c] + p] = e;
    }
}

// ---------------- model kernels ----------------
__global__ void h0_kernel(const float* __restrict__ x,
                          const float* __restrict__ w, const float* __restrict__ b) {
    int idx = blockIdx.x * blockDim.x + threadIdx.x;
    if (idx >= NN * 32) return;
    int n = idx >> 5, i = idx & 31;
    float acc = b[i];
#pragma unroll
    for (int f = 0; f < 3; f++) acc = fmaf(x[n * 3 + f], w[f * 32 + i], acc);
    g_h[idx] = acc;
}

// k2 = relu(relu(ea@W1+b1)@W2+b2), 3xTF32 mma, coalesced smem-staged stores.
__global__ void __launch_bounds__(256) k2_mma_kernel(
    const float* __restrict__ ea,
    const float* __restrict__ w1, const float* __restrict__ b1,
    const float* __restrict__ w2, const float* __restrict__ b2)
{
    __shared__ union { float t1f[32 * 129]; float kt[32 * 65]; } uk;
    __shared__ float As_b[32 * 36], As_s[32 * 36];
    __shared__ float w2s_b[32 * 72], w2s_s[32 * 72];
    __shared__ float b2s[64];

    int e0 = blockIdx.x * 32;
    int n0 = blockIdx.y * 64;
    int tid = threadIdx.x;

    if (tid < 64) b2s[tid] = b2[n0 + tid];
    // t1 fp32 (exact)
    for (int idx = tid; idx < 32 * 128; idx += 256) {
        int el = idx >> 7, j = idx & 127;
        float acc = b1[j];
#pragma unroll
        for (int f = 0; f < 6; f++) acc = fmaf(ea[(e0 + el) * 6 + f], w1[f * 128 + j], acc);
        uk.t1f[el * 129 + j] = fmaxf(acc, 0.f);
    }

    int w = tid >> 5, lane = tid & 31;
    int g = lane >> 2, tig = lane & 3;
    int wm = w & 1, wn = w >> 1;

    float acc[2][4] = {};

#pragma unroll 1
    for (int kb = 0; kb < 4; kb++) {
        __syncthreads();
        for (int idx = tid; idx < 1024; idx += 256) {
            int el = idx >> 5, kl = idx & 31;
            float v = uk.t1f[el * 129 + kb * 32 + kl];
            float b = tf32r(v);
            As_b[el * 36 + kl] = b;
            As_s[el * 36 + kl] = tf32r(v - b);
        }
        for (int idx = tid; idx < 2048; idx += 256) {
            int kl = idx >> 6, nl = idx & 63;
            float v = w2[(kb * 32 + kl) * 256 + n0 + nl];
            float b = tf32r(v);
            w2s_b[kl * 72 + nl] = b;
            w2s_s[kl * 72 + nl] = tf32r(v - b);
        }
        __syncthreads();
#pragma unroll
        for (int ks = 0; ks < 4; ks++) {
            int kk = ks * 8;
            unsigned ab[4], asr[4];
            int r0 = wm * 16 + g;
            ab[0]  = __float_as_uint(As_b[r0 * 36 + kk + tig]);
            ab[1]  = __float_as_uint(As_b[(r0 + 8) * 36 + kk + tig]);
            ab[2]  = __float_as_uint(As_b[r0 * 36 + kk + tig + 4]);
            ab[3]  = __float_as_uint(As_b[(r0 + 8) * 36 + kk + tig + 4]);
            asr[0] = __float_as_uint(As_s[r0 * 36 + kk + tig]);
            asr[1] = __float_as_uint(As_s[(r0 + 8) * 36 + kk + tig]);
            asr[2] = __float_as_uint(As_s[r0 * 36 + kk + tig + 4]);
            asr[3] = __float_as_uint(As_s[(r0 + 8) * 36 + kk + tig + 4]);
#pragma unroll
            for (int ni = 0; ni < 2; ni++) {
                int c0l = wn * 16 + ni * 8 + g;
                unsigned bb[2], bsr[2];
                bb[0]  = __float_as_uint(w2s_b[(kk + tig) * 72 + c0l]);
                bb[1]  = __float_as_uint(w2s_b[(kk + tig + 4) * 72 + c0l]);
                bsr[0] = __float_as_uint(w2s_s[(kk + tig) * 72 + c0l]);
                bsr[1] = __float_as_uint(w2s_s[(kk + tig + 4) * 72 + c0l]);
                mma_tf32(acc[ni], ab, bb);
                mma_tf32(acc[ni], ab, bsr);
                mma_tf32(acc[ni], asr, bb);
            }
        }
    }

    // stage result tile, then coalesced writeout
    __syncthreads();
    {
        int r = wm * 16 + g;
#pragma unroll
        for (int ni = 0; ni < 2; ni++) {
            int col = wn * 16 + ni * 8 + 2 * tig;
            uk.kt[r * 65 + col]           = acc[ni][0];
            uk.kt[r * 65 + col + 1]       = acc[ni][1];
            uk.kt[(r + 8) * 65 + col]     = acc[ni][2];
            uk.kt[(r + 8) * 65 + col + 1] = acc[ni][3];
        }
    }
    __syncthreads();
    for (int idx = tid; idx < 2048; idx += 256) {
        int row = idx >> 6, col = idx & 63;
        float v = fmaxf(uk.kt[row * 65 + col] + b2s[col], 0.f);
        g_k2[(size_t)(e0 + row) * 256 + n0 + col] = v;
    }
}

// G2[n][ci] = sum_j ker3[ci>>5][(ci&31)*32+j] * h[n][j], 3xTF32, node-major
// output with smem-staged coalesced stores.
__global__ void __launch_bounds__(256) G_mma_kernel(const float* __restrict__ k3w) {
    __shared__ float hs_b[64 * 36], hs_s[64 * 36];
    __shared__ union { struct { float b[32 * 72]; float s[32 * 72]; } bk; float Gt[64 * 65]; } u;

    int nn0 = blockIdx.x * 64;
    int ci0 = blockIdx.y * 64;
    int tid = threadIdx.x;

    for (int idx = tid; idx < 64 * 32; idx += 256) {
        int nl = idx >> 5, j = idx & 31;
        int n = nn0 + nl;
        float v = (n < NN) ? g_h[n * 32 + j] : 0.f;
        float b = tf32r(v);
        hs_b[nl * 36 + j] = b;
        hs_s[nl * 36 + j] = tf32r(v - b);
    }
    for (int idx = tid; idx < 32 * 64; idx += 256) {
        int cil = idx >> 5, j = idx & 31;
        int ci = ci0 + cil;
        float v = k3w[(size_t)(ci >> 5) * 1024 + (ci & 31) * 32 + j];
        float b = tf32r(v);
        u.bk.b[j * 72 + cil] = b;
        u.bk.s[j * 72 + cil] = tf32r(v - b);
    }
    __syncthreads();

    int w = tid >> 5, lane = tid & 31;
    int g = lane >> 2, tig = lane & 3;
    int wm = w & 1, wn = w >> 1;

    float acc[2][2][4] = {};

#pragma unroll
    for (int ks = 0; ks < 4; ks++) {
        int kk = ks * 8;
        unsigned ab[2][4], asr[2][4], bb[2][2], bsr[2][2];
#pragma unroll
        for (int mi = 0; mi < 2; mi++) {
            int r0 = wm * 32 + mi * 16 + g;
            ab[mi][0]  = __float_as_uint(hs_b[r0 * 36 + kk + tig]);
            ab[mi][1]  = __float_as_uint(hs_b[(r0 + 8) * 36 + kk + tig]);
            ab[mi][2]  = __float_as_uint(hs_b[r0 * 36 + kk + tig + 4]);
            ab[mi][3]  = __float_as_uint(hs_b[(r0 + 8) * 36 + kk + tig + 4]);
            asr[mi][0] = __float_as_uint(hs_s[r0 * 36 + kk + tig]);
            asr[mi][1] = __float_as_uint(hs_s[(r0 + 8) * 36 + kk + tig]);
            asr[mi][2] = __float_as_uint(hs_s[r0 * 36 + kk + tig + 4]);
            asr[mi][3] = __float_as_uint(hs_s[(r0 + 8) * 36 + kk + tig + 4]);
        }
#pragma unroll
        for (int ni = 0; ni < 2; ni++) {
            int c0l = wn * 16 + ni * 8 + g;
            bb[ni][0]  = __float_as_uint(u.bk.b[(kk + tig) * 72 + c0l]);
            bb[ni][1]  = __float_as_uint(u.bk.b[(kk + tig + 4) * 72 + c0l]);
            bsr[ni][0] = __float_as_uint(u.bk.s[(kk + tig) * 72 + c0l]);
            bsr[ni][1] = __float_as_uint(u.bk.s[(kk + tig + 4) * 72 + c0l]);
        }
#pragma unroll
        for (int mi = 0; mi < 2; mi++)
#pragma unroll
            for (int ni = 0; ni < 2; ni++) {
                mma_tf32(acc[mi][ni], ab[mi], bb[ni]);
                mma_tf32(acc[mi][ni], ab[mi], bsr[ni]);
                mma_tf32(acc[mi][ni], asr[mi], bb[ni]);
            }
    }

    // stage tile, then coalesced node-major writeout
    __syncthreads();
#pragma unroll
    for (int mi = 0; mi < 2; mi++) {
        int rl = wm * 32 + mi * 16 + g;
#pragma unroll
        for (int ni = 0; ni < 2; ni++) {
            int cl = wn * 16 + ni * 8 + 2 * tig;
            u.Gt[rl * 65 + cl]           = acc[mi][ni][0];
            u.Gt[rl * 65 + cl + 1]       = acc[mi][ni][1];
            u.Gt[(rl + 8) * 65 + cl]     = acc[mi][ni][2];
            u.Gt[(rl + 8) * 65 + cl + 1] = acc[mi][ni][3];
        }
    }
    __syncthreads();
    for (int idx = tid; idx < 4096; idx += 256) {
        int row = idx >> 6, col = idx & 63;
        int n = nn0 + row;
        if (n < NN) g_G2[(size_t)n * 8192 + ci0 + col] = u.Gt[row * 65 + col];
    }
}

// Bias[n][i] = sum_j ker3_b[i*32+j] * h[n][j]  (exact fp32)
__global__ void bias_kernel(const float* __restrict__ b3) {
    int idx = blockIdx.x * blockDim.x + threadIdx.x;
    if (idx >= NN * 32) return;
    int n = idx >> 5, i = idx & 31;
    float acc = 0.f;
#pragma unroll
    for (int j = 0; j < 32; j++) acc = fmaf(b3[i * 32 + j], g_h[n * 32 + j], acc);
    g_Bias[idx] = acc;
}

// Edge kernel: one block per destination node. G2 (32KB, contiguous) cached in
// smem; per warp 4 edges; lanes = 8 i-quads x 4 c-groups; inner pass =
// 1 LDS.128 (G) + 4 broadcast LDS (k2) + 16 FMA. No shuffles in hot loop.
#define SMEM_EDGE_FLOATS 18884
__global__ void __launch_bounds__(256) edge_kernel(
    const void* __restrict__ ei,
    const float* __restrict__ cm1w, const float* __restrict__ cm1b,
    const float* __restrict__ cm2w, const float* __restrict__ cm2b)
{
    int n = blockIdx.x;
    int cs0 = g_colstart[n];
    int deg = g_colstart[n + 1] - cs0;
    if (deg == 0) return;

    extern __shared__ float sm[];
    float* G2s   = sm;             // 8192
    float* k2s   = sm + 8192;      // 32*260 = 8320
    float* cm1s  = sm + 16512;     // 32*33 = 1056
    float* ms_   = sm + 17568;     // 32*36 = 1152
    float* Bs    = sm + 18720;     // 32
    float* cm1bs = sm + 18752;     // 32
    float* cm2s  = sm + 18784;     // 32
    int*   es    = (int*)(sm + 18816);  // 32
    int*   rs    = (int*)(sm + 18848);  // 32
    float* ccolp = sm + 18880;     // ccol[3], cm2b0 at [3]

    int tid = threadIdx.x, w = tid >> 5, lane = tid & 31;
    int is64 = g_is64;

    {
        const float4* src = (const float4*)(g_G2 + (size_t)n * 8192);
        float4* dst = (float4*)G2s;
        for (int idx = tid; idx < 2048; idx += 256) dst[idx] = src[idx];
    }
    for (int idx = tid; idx < 1024; idx += 256)
        cm1s[(idx >> 5) * 33 + (idx & 31)] = cm1w[idx];
    if (tid < 32) { Bs[tid] = g_Bias[n * 32 + tid]; cm1bs[tid] = cm1b[tid]; cm2s[tid] = cm2w[tid]; }
    if (tid < 3) ccolp[tid] = g_coord[n * 3 + tid];
    if (tid == 0) ccolp[3] = cm2b[0];

    int lg = lane >> 3;   // c-group
    int iq = lane & 7;    // i-quad
    const unsigned full = 0xffffffffu;

    for (int base = 0; base < deg; base += 32) {
        __syncthreads();
        if (tid < 32) {
            int p = base + tid;
            int e = (p < deg) ? g_perm[cs0 + p] : -1;
            es[tid] = e;
            rs[tid] = (e >= 0) ? eidx(ei, e, is64) : 0;
        }
        __syncthreads();
        for (int idx = tid; idx < 2048; idx += 256) {
            int el = idx >> 6, c4 = idx & 63;
            int e = es[el];
            float4 v = (e >= 0) ? ((const float4*)g_k2)[(size_t)e * 64 + c4]
                                : make_float4(0.f, 0.f, 0.f, 0.f);
            *(float4*)&k2s[el * 260 + c4 * 4] = v;
        }
        __syncthreads();

        int e_l0 = w * 4;
        float acc[4][4] = {};
        const float4* G4 = (const float4*)G2s;
#pragma unroll 4
        for (int cb = 0; cb < 64; cb++) {
            int c = cb * 4 + lg;
            float4 gv = G4[c * 8 + iq];
            float k0 = k2s[(e_l0 + 0) * 260 + c];
            float k1 = k2s[(e_l0 + 1) * 260 + c];
            float k2v = k2s[(e_l0 + 2) * 260 + c];
            float k3 = k2s[(e_l0 + 3) * 260 + c];
            acc[0][0] = fmaf(k0, gv.x, acc[0][0]); acc[0][1] = fmaf(k0, gv.y, acc[0][1]);
            acc[0][2] = fmaf(k0, gv.z, acc[0][2]); acc[0][3] = fmaf(k0, gv.w, acc[0][3]);
            acc[1][0] = fmaf(k1, gv.x, acc[1][0]); acc[1][1] = fmaf(k1, gv.y, acc[1][1]);
            acc[1][2] = fmaf(k1, gv.z, acc[1][2]); acc[1][3] = fmaf(k1, gv.w, acc[1][3]);
            acc[2][0] = fmaf(k2v, gv.x, acc[2][0]); acc[2][1] = fmaf(k2v, gv.y, acc[2][1]);
            acc[2][2] = fmaf(k2v, gv.z, acc[2][2]); acc[2][3] = fmaf(k2v, gv.w, acc[2][3]);
            acc[3][0] = fmaf(k3, gv.x, acc[3][0]); acc[3][1] = fmaf(k3, gv.y, acc[3][1]);
            acc[3][2] = fmaf(k3, gv.z, acc[3][2]); acc[3][3] = fmaf(k3, gv.w, acc[3][3]);
        }
        // reduce across the 4 c-groups
#pragma unroll
        for (int q = 0; q < 4; q++)
#pragma unroll
            for (int c = 0; c < 4; c++) {
                acc[q][c] += __shfl_xor_sync(full, acc[q][c], 8);
                acc[q][c] += __shfl_xor_sync(full, acc[q][c], 16);
            }
        if (lane < 8) {
#pragma unroll
            for (int q = 0; q < 4; q++)
                *(float4*)&ms_[(e_l0 + q) * 36 + iq * 4] =
                    make_float4(acc[q][0], acc[q][1], acc[q][2], acc[q][3]);
        }
        __syncwarp();
        // add bias, agg atomics (coalesced 128B lines)
#pragma unroll
        for (int q = 0; q < 4; q++) {
            int el = e_l0 + q;
            float mf = ms_[el * 36 + lane] + Bs[lane];
            ms_[el * 36 + lane] = mf;
            if (es[el] >= 0) atomicAdd(&g_agg[rs[el] * 32 + lane], mf);
        }
        __syncwarp();
        // coord-weight MLP + coord atomics
#pragma unroll 1
        for (int q = 0; q < 4; q++) {
            int el = e_l0 + q;
            float t = cm1bs[lane];
#pragma unroll
            for (int i = 0; i < 32; i++)
                t = fmaf(ms_[el * 36 + i], cm1s[i * 33 + lane], t);
            t = fmaxf(t, 0.f) * cm2s[lane];
#pragma unroll
            for (int off = 16; off; off >>= 1) t += __shfl_xor_sync(full, t, off);
            int e = es[el];
            if (e >= 0 && lane < 3) {
                float we = t + ccolp[3];
                int r = rs[el];
                atomicAdd(&g_cacc[r * 3 + lane], (g_coord[r * 3 + lane] - ccolp[lane]) * we);
            }
        }
    }
}

__global__ void node_kernel() {
    int idx = blockIdx.x * blockDim.x + threadIdx.x;
    if (idx >= NN * 32) return;
    int n = idx >> 5, i = idx & 31;
    float cf = g_cntf[n];
    float hv = g_h[idx] + g_agg[idx] / cf;
    g_h[idx] = fmaxf(hv, 0.f);
    if (i < 3) g_coord[n * 3 + i] += g_cacc[n * 3 + i] / cf;
}

__global__ void out_kernel(const float* __restrict__ aw, const float* __restrict__ ab,
                           const float* __restrict__ bw, const float* __restrict__ bb,
                           float* __restrict__ out, int out_size) {
    int n = blockIdx.x * blockDim.x + threadIdx.x;
    if (n >= NN) return;
    float h[32];
    const float4* hp = (const float4*)(g_h + n * 32);
#pragma unroll
    for (int q = 0; q < 8; q++) {
        float4 v = hp[q];
        h[q * 4] = v.x; h[q * 4 + 1] = v.y; h[q * 4 + 2] = v.z; h[q * 4 + 3] = v.w;
    }
    float acc = bb[0];
#pragma unroll 4
    for (int j = 0; j < 64; j++) {
        float t = ab[j];
#pragma unroll
        for (int i = 0; i < 32; i++) t = fmaf(h[i], aw[i * 64 + j], t);
        acc = fmaf(fmaxf(t, 0.f), bw[j], acc);
    }
    out[n] = acc;
#pragma unroll
    for (int d = 0; d < 3; d++) {
        int idx = NN + n * 3 + d;
        if (idx < out_size) out[idx] = g_coord[n * 3 + d];
    }
}

// ---------------- launch ----------------
extern "C" void kernel_launch(void* const* d_in, const int* in_sizes, int n_in,
                              void* d_out, int out_size) {
    const float* x      = (const float*)d_in[0];
    const void*  ei     = d_in[1];
    const float* ea     = (const float*)d_in[2];
    const float* ci     = (const float*)d_in[3];
    const float* fc1w   = (const float*)d_in[4];
    const float* fc1b   = (const float*)d_in[5];
    const float* k1w    = (const float*)d_in[6];
    const float* k1b    = (const float*)d_in[7];
    const float* k2w    = (const float*)d_in[8];
    const float* k2b    = (const float*)d_in[9];
    const float* k3w    = (const float*)d_in[10];
    const float* k3b    = (const float*)d_in[11];
    const float* cm1w   = (const float*)d_in[12];
    const float* cm1b   = (const float*)d_in[13];
    const float* cm2w   = (const float*)d_in[14];
    const float* cm2b   = (const float*)d_in[15];
    const float* fc2aw  = (const float*)d_in[16];
    const float* fc2ab  = (const float*)d_in[17];
    const float* fc2bw  = (const float*)d_in[18];
    const float* fc2bb  = (const float*)d_in[19];
    float* out = (float*)d_out;

    static int smem_set = 0;
    if (!smem_set) {
        cudaFuncSetAttribute(edge_kernel, cudaFuncAttributeMaxDynamicSharedMemorySize,
                             SMEM_EDGE_FLOATS * 4);
        smem_set = 1;
    }

    detect_kernel<<<1, 32>>>(ei);
    zero_sort_kernel<<<(NN + 255) / 256, 256>>>();
    hist_kernel<<<(EE + 255) / 256, 256>>>(ei);
    scan_kernel<<<1, 1024>>>();
    cntf_kernel<<<(NN + 255) / 256, 256>>>();
    scatter_kernel<<<(EE + 255) / 256, 256>>>(ei);

    coordinit_kernel<<<(NN * 3 + 255) / 256, 256>>>(ci);
    h0_kernel<<<(NN * 32 + 255) / 256, 256>>>(x, fc1w, fc1b);
    k2_mma_kernel<<<dim3(EE / 32, 4), 256>>>(ea, k1w, k1b, k2w, k2b);

    for (int layer = 0; layer < 4; layer++) {
        G_mma_kernel<<<dim3((NN + 63) / 64, 128), 256>>>(k3w);
        bias_kernel<<<(NN * 32 + 255) / 256, 256>>>(k3b);
        zero_acc_kernel<<<(NN * 32 + 255) / 256, 256>>>();
        edge_kernel<<<NN, 256, SMEM_EDGE_FLOATS * 4>>>(ei, cm1w, cm1b, cm2w, cm2b);
        node_kernel<<<(NN * 32 + 255) / 256, 256>>>();
    }

    out_kernel<<<(NN + 255) / 256, 256>>>(fc2aw, fc2ab, fc2bw, fc2bb, out, out_size);
}

// round 9
// speedup vs baseline: 1.1866x; 1.0521x over previous
#include <cuda_runtime.h>

#define NN 10000
#define EE 300000
#define NPB 4   // nodes per edge-kernel block

// ---------------- scratch (__device__ globals, no allocs) ----------------
__device__ __align__(16) float g_h[NN * 32];
__device__ __align__(16) float g_k2[(size_t)EE * 256];
__device__ __align__(16) float g_G2[(size_t)NN * 8192];   // [n][c*32+i] node-major
__device__ __align__(16) float g_Bias[NN * 32];
__device__ __align__(16) float g_agg[NN * 32];
__device__ __align__(16) float g_cacc[NN * 3];
__device__ __align__(16) float g_coord[NN * 3];
__device__ float g_cntf[NN];
__device__ int   g_colcnt[NN];
__device__ int   g_rowcnt[NN];
__device__ int   g_cursor[NN];
__device__ int   g_colstart[NN + 1];
__device__ int   g_perm[EE];
__device__ int   g_is64;

// ---------------- tf32 / async helpers ----------------
__device__ __forceinline__ float tf32r(float f) {
    unsigned r;
    asm("cvt.rna.tf32.f32 %0, %1;" : "=r"(r) : "f"(f));
    return __uint_as_float(r);
}

__device__ __forceinline__ void mma_tf32(float* c, const unsigned* a, const unsigned* b) {
    asm volatile(
        "mma.sync.aligned.m16n8k8.row.col.f32.tf32.tf32.f32 "
        "{%0,%1,%2,%3}, {%4,%5,%6,%7}, {%8,%9}, {%0,%1,%2,%3};"
        : "+f"(c[0]), "+f"(c[1]), "+f"(c[2]), "+f"(c[3])
        : "r"(a[0]), "r"(a[1]), "r"(a[2]), "r"(a[3]), "r"(b[0]), "r"(b[1]));
}

__device__ __forceinline__ void cp_async16(void* smem_dst, const void* gmem_src) {
    unsigned s = (unsigned)__cvta_generic_to_shared(smem_dst);
    asm volatile("cp.async.cg.shared.global [%0], [%1], 16;\n" :: "r"(s), "l"(gmem_src));
}
#define CP_COMMIT() asm volatile("cp.async.commit_group;\n" ::)
#define CP_WAIT(N)  asm volatile("cp.async.wait_group %0;\n" :: "n"(N))

// ---------------- edge-index dtype handling ----------------
__global__ void detect_kernel(const void* __restrict__ ei) {
    const int* w = (const int*)ei;
    int lane = threadIdx.x;
    int hi = w[2 * lane + 1];
    unsigned any = __ballot_sync(0xffffffffu, hi != 0);
    if (lane == 0) g_is64 = (any == 0u) ? 1 : 0;
}

__device__ __forceinline__ int eidx(const void* __restrict__ ei, long long pos, int is64) {
    int v = is64 ? (int)((const long long*)ei)[pos] : ((const int*)ei)[pos];
    return min(max(v, 0), NN - 1);
}

// ---------------- small utility kernels ----------------
__global__ void zero_sort_kernel() {
    int i = blockIdx.x * blockDim.x + threadIdx.x;
    if (i < NN) { g_colcnt[i] = 0; g_rowcnt[i] = 0; g_cursor[i] = 0; }
}

__global__ void coordinit_kernel(const float* __restrict__ ci) {
    int i = blockIdx.x * blockDim.x + threadIdx.x;
    if (i < NN * 3) g_coord[i] = ci[i];
}

__global__ void hist_kernel(const void* __restrict__ ei) {
    int e = blockIdx.x * blockDim.x + threadIdx.x;
    int is64 = g_is64;
    if (e < EE) {
        atomicAdd(&g_rowcnt[eidx(ei, e, is64)], 1);
        atomicAdd(&g_colcnt[eidx(ei, (long long)EE + e, is64)], 1);
    }
}

__global__ void cntf_kernel() {
    int n = blockIdx.x * blockDim.x + threadIdx.x;
    if (n < NN) g_cntf[n] = fmaxf(1.f, (float)g_rowcnt[n]);
}

__global__ void scan_kernel() {
    const int BPT = 10;
    int t = threadIdx.x;
    int loc[BPT];
    int s = 0;
#pragma unroll
    for (int j = 0; j < BPT; j++) {
        int b = t * BPT + j;
        int v = (b < NN) ? g_colcnt[b] : 0;
        loc[j] = s; s += v;
    }
    unsigned full = 0xffffffffu;
    int lane = t & 31, wid = t >> 5;
    int v = s;
#pragma unroll
    for (int o = 1; o < 32; o <<= 1) {
        int u = __shfl_up_sync(full, v, o);
        if (lane >= o) v += u;
    }
    __shared__ int wsum[32];
    if (lane == 31) wsum[wid] = v;
    __syncthreads();
    if (wid == 0) {
        int x = wsum[lane];
#pragma unroll
        for (int o = 1; o < 32; o <<= 1) {
            int u = __shfl_up_sync(full, x, o);
            if (lane >= o) x += u;
        }
        wsum[lane] = x;
    }
    __syncthreads();
    int excl = v - s + (wid ? wsum[wid - 1] : 0);
#pragma unroll
    for (int j = 0; j < BPT; j++) {
        int b = t * BPT + j;
        if (b < NN) g_colstart[b] = excl + loc[j];
    }
    if (t == 1023) g_colstart[NN] = wsum[31];
}

__global__ void scatter_kernel(const void* __restrict__ ei) {
    int e = blockIdx.x * blockDim.x + threadIdx.x;
    if (e < EE) {
        int c = eidx(ei, (long long)EE + e, g_is64);
        int p = atomicAdd(&g_cursor[c], 1);
        g_perm[g_colstart[c] + p] = e;
    }
}

// ---------------- model kernels ----------------
__global__ void h0_kernel(const float* __restrict__ x,
                          const float* __restrict__ w, const float* __restrict__ b) {
    int idx = blockIdx.x * blockDim.x + threadIdx.x;
    if (idx >= NN * 32) return;
    int n = idx >> 5, i = idx & 31;
    float acc = b[i];
#pragma unroll
    for (int f = 0; f < 3; f++) acc = fmaf(x[n * 3 + f], w[f * 32 + i], acc);
    g_h[idx] = acc;
}

// k2 = relu(relu(ea@W1+b1)@W2+b2), 3xTF32 mma, coalesced smem-staged stores.
__global__ void __launch_bounds__(256) k2_mma_kernel(
    const float* __restrict__ ea,
    const float* __restrict__ w1, const float* __restrict__ b1,
    const float* __restrict__ w2, const float* __restrict__ b2)
{
    __shared__ union { float t1f[32 * 129]; float kt[32 * 65]; } uk;
    __shared__ float As_b[32 * 36], As_s[32 * 36];
    __shared__ float w2s_b[32 * 72], w2s_s[32 * 72];
    __shared__ float b2s[64];

    int e0 = blockIdx.x * 32;
    int n0 = blockIdx.y * 64;
    int tid = threadIdx.x;

    if (tid < 64) b2s[tid] = b2[n0 + tid];
    for (int idx = tid; idx < 32 * 128; idx += 256) {
        int el = idx >> 7, j = idx & 127;
        float acc = b1[j];
#pragma unroll
        for (int f = 0; f < 6; f++) acc = fmaf(ea[(e0 + el) * 6 + f], w1[f * 128 + j], acc);
        uk.t1f[el * 129 + j] = fmaxf(acc, 0.f);
    }

    int w = tid >> 5, lane = tid & 31;
    int g = lane >> 2, tig = lane & 3;
    int wm = w & 1, wn = w >> 1;

    float acc[2][4] = {};

#pragma unroll 1
    for (int kb = 0; kb < 4; kb++) {
        __syncthreads();
        for (int idx = tid; idx < 1024; idx += 256) {
            int el = idx >> 5, kl = idx & 31;
            float v = uk.t1f[el * 129 + kb * 32 + kl];
            float b = tf32r(v);
            As_b[el * 36 + kl] = b;
            As_s[el * 36 + kl] = tf32r(v - b);
        }
        for (int idx = tid; idx < 2048; idx += 256) {
            int kl = idx >> 6, nl = idx & 63;
            float v = w2[(kb * 32 + kl) * 256 + n0 + nl];
            float b = tf32r(v);
            w2s_b[kl * 72 + nl] = b;
            w2s_s[kl * 72 + nl] = tf32r(v - b);
        }
        __syncthreads();
#pragma unroll
        for (int ks = 0; ks < 4; ks++) {
            int kk = ks * 8;
            unsigned ab[4], asr[4];
            int r0 = wm * 16 + g;
            ab[0]  = __float_as_uint(As_b[r0 * 36 + kk + tig]);
            ab[1]  = __float_as_uint(As_b[(r0 + 8) * 36 + kk + tig]);
            ab[2]  = __float_as_uint(As_b[r0 * 36 + kk + tig + 4]);
            ab[3]  = __float_as_uint(As_b[(r0 + 8) * 36 + kk + tig + 4]);
            asr[0] = __float_as_uint(As_s[r0 * 36 + kk + tig]);
            asr[1] = __float_as_uint(As_s[(r0 + 8) * 36 + kk + tig]);
            asr[2] = __float_as_uint(As_s[r0 * 36 + kk + tig + 4]);
            asr[3] = __float_as_uint(As_s[(r0 + 8) * 36 + kk + tig + 4]);
#pragma unroll
            for (int ni = 0; ni < 2; ni++) {
                int c0l = wn * 16 + ni * 8 + g;
                unsigned bb[2], bsr[2];
                bb[0]  = __float_as_uint(w2s_b[(kk + tig) * 72 + c0l]);
                bb[1]  = __float_as_uint(w2s_b[(kk + tig + 4) * 72 + c0l]);
                bsr[0] = __float_as_uint(w2s_s[(kk + tig) * 72 + c0l]);
                bsr[1] = __float_as_uint(w2s_s[(kk + tig + 4) * 72 + c0l]);
                mma_tf32(acc[ni], ab, bb);
                mma_tf32(acc[ni], ab, bsr);
                mma_tf32(acc[ni], asr, bb);
            }
        }
    }

    __syncthreads();
    {
        int r = wm * 16 + g;
#pragma unroll
        for (int ni = 0; ni < 2; ni++) {
            int col = wn * 16 + ni * 8 + 2 * tig;
            uk.kt[r * 65 + col]           = acc[ni][0];
            uk.kt[r * 65 + col + 1]       = acc[ni][1];
            uk.kt[(r + 8) * 65 + col]     = acc[ni][2];
            uk.kt[(r + 8) * 65 + col + 1] = acc[ni][3];
        }
    }
    __syncthreads();
    for (int idx = tid; idx < 2048; idx += 256) {
        int row = idx >> 6, col = idx & 63;
        float v = fmaxf(uk.kt[row * 65 + col] + b2s[col], 0.f);
        g_k2[(size_t)(e0 + row) * 256 + n0 + col] = v;
    }
}

// G2[n][ci] = sum_j ker3[ci>>5][(ci&31)*32+j] * h[n][j], 3xTF32, node-major.
__global__ void __launch_bounds__(256) G_mma_kernel(const float* __restrict__ k3w) {
    __shared__ float hs_b[64 * 36], hs_s[64 * 36];
    __shared__ union { struct { float b[32 * 72]; float s[32 * 72]; } bk; float Gt[64 * 65]; } u;

    int nn0 = blockIdx.x * 64;
    int ci0 = blockIdx.y * 64;
    int tid = threadIdx.x;

    for (int idx = tid; idx < 64 * 32; idx += 256) {
        int nl = idx >> 5, j = idx & 31;
        int n = nn0 + nl;
        float v = (n < NN) ? g_h[n * 32 + j] : 0.f;
        float b = tf32r(v);
        hs_b[nl * 36 + j] = b;
        hs_s[nl * 36 + j] = tf32r(v - b);
    }
    for (int idx = tid; idx < 32 * 64; idx += 256) {
        int cil = idx >> 5, j = idx & 31;
        int ci = ci0 + cil;
        float v = k3w[(size_t)(ci >> 5) * 1024 + (ci & 31) * 32 + j];
        float b = tf32r(v);
        u.bk.b[j * 72 + cil] = b;
        u.bk.s[j * 72 + cil] = tf32r(v - b);
    }
    __syncthreads();

    int w = tid >> 5, lane = tid & 31;
    int g = lane >> 2, tig = lane & 3;
    int wm = w & 1, wn = w >> 1;

    float acc[2][2][4] = {};

#pragma unroll
    for (int ks = 0; ks < 4; ks++) {
        int kk = ks * 8;
        unsigned ab[2][4], asr[2][4], bb[2][2], bsr[2][2];
#pragma unroll
        for (int mi = 0; mi < 2; mi++) {
            int r0 = wm * 32 + mi * 16 + g;
            ab[mi][0]  = __float_as_uint(hs_b[r0 * 36 + kk + tig]);
            ab[mi][1]  = __float_as_uint(hs_b[(r0 + 8) * 36 + kk + tig]);
            ab[mi][2]  = __float_as_uint(hs_b[r0 * 36 + kk + tig + 4]);
            ab[mi][3]  = __float_as_uint(hs_b[(r0 + 8) * 36 + kk + tig + 4]);
            asr[mi][0] = __float_as_uint(hs_s[r0 * 36 + kk + tig]);
            asr[mi][1] = __float_as_uint(hs_s[(r0 + 8) * 36 + kk + tig]);
            asr[mi][2] = __float_as_uint(hs_s[r0 * 36 + kk + tig + 4]);
            asr[mi][3] = __float_as_uint(hs_s[(r0 + 8) * 36 + kk + tig + 4]);
        }
#pragma unroll
        for (int ni = 0; ni < 2; ni++) {
            int c0l = wn * 16 + ni * 8 + g;
            bb[ni][0]  = __float_as_uint(u.bk.b[(kk + tig) * 72 + c0l]);
            bb[ni][1]  = __float_as_uint(u.bk.b[(kk + tig + 4) * 72 + c0l]);
            bsr[ni][0] = __float_as_uint(u.bk.s[(kk + tig) * 72 + c0l]);
            bsr[ni][1] = __float_as_uint(u.bk.s[(kk + tig + 4) * 72 + c0l]);
        }
#pragma unroll
        for (int mi = 0; mi < 2; mi++)
#pragma unroll
            for (int ni = 0; ni < 2; ni++) {
                mma_tf32(acc[mi][ni], ab[mi], bb[ni]);
                mma_tf32(acc[mi][ni], ab[mi], bsr[ni]);
                mma_tf32(acc[mi][ni], asr[mi], bb[ni]);
            }
    }

    __syncthreads();
#pragma unroll
    for (int mi = 0; mi < 2; mi++) {
        int rl = wm * 32 + mi * 16 + g;
#pragma unroll
        for (int ni = 0; ni < 2; ni++) {
            int cl = wn * 16 + ni * 8 + 2 * tig;
            u.Gt[rl * 65 + cl]           = acc[mi][ni][0];
            u.Gt[rl * 65 + cl + 1]       = acc[mi][ni][1];
            u.Gt[(rl + 8) * 65 + cl]     = acc[mi][ni][2];
            u.Gt[(rl + 8) * 65 + cl + 1] = acc[mi][ni][3];
        }
    }
    __syncthreads();
    for (int idx = tid; idx < 4096; idx += 256) {
        int row = idx >> 6, col = idx & 63;
        int n = nn0 + row;
        if (n < NN) g_G2[(size_t)n * 8192 + ci0 + col] = u.Gt[row * 65 + col];
    }
}

// Bias[n][i] = sum_j ker3_b[i*32+j] * h[n][j] (exact fp32); zero agg/cacc.
__global__ void bias_zero_kernel(const float* __restrict__ b3) {
    int idx = blockIdx.x * blockDim.x + threadIdx.x;
    if (idx < NN * 3) g_cacc[idx] = 0.f;
    if (idx >= NN * 32) return;
    int n = idx >> 5, i = idx & 31;
    float acc = 0.f;
#pragma unroll
    for (int j = 0; j < 32; j++) acc = fmaf(b3[i * 32 + j], g_h[n * 32 + j], acc);
    g_Bias[idx] = acc;
    g_agg[idx] = 0.f;
}

// Edge kernel v3: NPB nodes per block, cp.async double-buffered G2 prefetch.
// Per warp 4 edges; lanes = 8 i-quads x 4 c-groups; no shuffles in hot loop.
#define SMEM_EDGE_FLOATS 27080
__global__ void __launch_bounds__(256) edge_kernel(
    const void* __restrict__ ei,
    const float* __restrict__ cm1w, const float* __restrict__ cm1b,
    const float* __restrict__ cm2w, const float* __restrict__ cm2b)
{
    extern __shared__ float sm[];
    float* Gb0   = sm;                  // 8192
    float* Gb1   = sm + 8192;           // 8192
    float* k2s   = sm + 16384;          // 32*260 = 8320
    float* cm1s  = sm + 24704;          // 32*33 = 1056
    float* ms_   = sm + 25760;          // 32*36 = 1152
    float* Bs    = sm + 26912;          // 32
    float* cm1bs = sm + 26944;          // 32
    float* cm2s  = sm + 26976;          // 32
    int*   es    = (int*)(sm + 27008);  // 32
    int*   rs    = (int*)(sm + 27040);  // 32
    float* ccolp = sm + 27072;          // [0..2]=ccol, [3]=cm2b0

    int tid = threadIdx.x, w = tid >> 5, lane = tid & 31;
    int is64 = g_is64;
    int n0 = blockIdx.x * NPB;

    for (int idx = tid; idx < 1024; idx += 256)
        cm1s[(idx >> 5) * 33 + (idx & 31)] = cm1w[idx];
    if (tid < 32) { cm1bs[tid] = cm1b[tid]; cm2s[tid] = cm2w[tid]; }
    if (tid == 0) ccolp[3] = cm2b[0];

    // prefetch G2 of first node
    {
        const float* src = g_G2 + (size_t)n0 * 8192;
        for (int idx = tid; idx < 2048; idx += 256)
            cp_async16(Gb0 + idx * 4, src + idx * 4);
        CP_COMMIT();
    }

    int lg = lane >> 3;   // c-group
    int iq = lane & 7;    // i-quad
    const unsigned full = 0xffffffffu;

#pragma unroll 1
    for (int t = 0; t < NPB; t++) {
        int n = n0 + t;
        float* G2s = (t & 1) ? Gb1 : Gb0;
        if (t + 1 < NPB) {
            float* nxt = (t & 1) ? Gb0 : Gb1;
            const float* src = g_G2 + (size_t)(n + 1) * 8192;
            for (int idx = tid; idx < 2048; idx += 256)
                cp_async16(nxt + idx * 4, src + idx * 4);
            CP_COMMIT();
            CP_WAIT(1);
        } else {
            CP_WAIT(0);
        }
        if (tid < 32) Bs[tid] = g_Bias[n * 32 + tid];
        if (tid < 3) ccolp[tid] = g_coord[n * 3 + tid];
        __syncthreads();

        int cs0 = g_colstart[n];
        int deg = g_colstart[n + 1] - cs0;

        for (int base = 0; base < deg; base += 32) {
            if (base) __syncthreads();
            if (tid < 32) {
                int p = base + tid;
                int e = (p < deg) ? g_perm[cs0 + p] : -1;
                es[tid] = e;
                rs[tid] = (e >= 0) ? eidx(ei, e, is64) : 0;
            }
            __syncthreads();
            for (int idx = tid; idx < 2048; idx += 256) {
                int el = idx >> 6, c4 = idx & 63;
                int e = es[el];
                float4 v = (e >= 0) ? ((const float4*)g_k2)[(size_t)e * 64 + c4]
                                    : make_float4(0.f, 0.f, 0.f, 0.f);
                *(float4*)&k2s[el * 260 + c4 * 4] = v;
            }
            __syncthreads();

            int e_l0 = w * 4;
            float acc[4][4] = {};
            const float4* G4 = (const float4*)G2s;
#pragma unroll 4
            for (int cb = 0; cb < 64; cb++) {
                int c = cb * 4 + lg;
                float4 gv = G4[c * 8 + iq];
                float k0 = k2s[(e_l0 + 0) * 260 + c];
                float k1 = k2s[(e_l0 + 1) * 260 + c];
                float k2v = k2s[(e_l0 + 2) * 260 + c];
                float k3 = k2s[(e_l0 + 3) * 260 + c];
                acc[0][0] = fmaf(k0, gv.x, acc[0][0]); acc[0][1] = fmaf(k0, gv.y, acc[0][1]);
                acc[0][2] = fmaf(k0, gv.z, acc[0][2]); acc[0][3] = fmaf(k0, gv.w, acc[0][3]);
                acc[1][0] = fmaf(k1, gv.x, acc[1][0]); acc[1][1] = fmaf(k1, gv.y, acc[1][1]);
                acc[1][2] = fmaf(k1, gv.z, acc[1][2]); acc[1][3] = fmaf(k1, gv.w, acc[1][3]);
                acc[2][0] = fmaf(k2v, gv.x, acc[2][0]); acc[2][1] = fmaf(k2v, gv.y, acc[2][1]);
                acc[2][2] = fmaf(k2v, gv.z, acc[2][2]); acc[2][3] = fmaf(k2v, gv.w, acc[2][3]);
                acc[3][0] = fmaf(k3, gv.x, acc[3][0]); acc[3][1] = fmaf(k3, gv.y, acc[3][1]);
                acc[3][2] = fmaf(k3, gv.z, acc[3][2]); acc[3][3] = fmaf(k3, gv.w, acc[3][3]);
            }
#pragma unroll
            for (int q = 0; q < 4; q++)
#pragma unroll
                for (int c = 0; c < 4; c++) {
                    acc[q][c] += __shfl_xor_sync(full, acc[q][c], 8);
                    acc[q][c] += __shfl_xor_sync(full, acc[q][c], 16);
                }
            if (lane < 8) {
#pragma unroll
                for (int q = 0; q < 4; q++)
                    *(float4*)&ms_[(e_l0 + q) * 36 + iq * 4] =
                        make_float4(acc[q][0], acc[q][1], acc[q][2], acc[q][3]);
            }
            __syncwarp();
#pragma unroll
            for (int q = 0; q < 4; q++) {
                int el = e_l0 + q;
                float mf = ms_[el * 36 + lane] + Bs[lane];
                ms_[el * 36 + lane] = mf;
                if (es[el] >= 0) atomicAdd(&g_agg[rs[el] * 32 + lane], mf);
            }
            __syncwarp();
#pragma unroll 1
            for (int q = 0; q < 4; q++) {
                int el = e_l0 + q;
                float tt = cm1bs[lane];
#pragma unroll
                for (int i = 0; i < 32; i++)
                    tt = fmaf(ms_[el * 36 + i], cm1s[i * 33 + lane], tt);
                tt = fmaxf(tt, 0.f) * cm2s[lane];
#pragma unroll
                for (int off = 16; off; off >>= 1) tt += __shfl_xor_sync(full, tt, off);
                int e = es[el];
                if (e >= 0 && lane < 3) {
                    float we = tt + ccolp[3];
                    int r = rs[el];
                    atomicAdd(&g_cacc[r * 3 + lane], (g_coord[r * 3 + lane] - ccolp[lane]) * we);
                }
            }
        }
        __syncthreads();   // all warps done with this node's buffers before next prefetch
    }
}

__global__ void node_kernel() {
    int idx = blockIdx.x * blockDim.x + threadIdx.x;
    if (idx >= NN * 32) return;
    int n = idx >> 5, i = idx & 31;
    float cf = g_cntf[n];
    float hv = g_h[idx] + g_agg[idx] / cf;
    g_h[idx] = fmaxf(hv, 0.f);
    if (i < 3) g_coord[n * 3 + i] += g_cacc[n * 3 + i] / cf;
}

__global__ void out_kernel(const float* __restrict__ aw, const float* __restrict__ ab,
                           const float* __restrict__ bw, const float* __restrict__ bb,
                           float* __restrict__ out, int out_size) {
    int n = blockIdx.x * blockDim.x + threadIdx.x;
    if (n >= NN) return;
    float h[32];
    const float4* hp = (const float4*)(g_h + n * 32);
#pragma unroll
    for (int q = 0; q < 8; q++) {
        float4 v = hp[q];
        h[q * 4] = v.x; h[q * 4 + 1] = v.y; h[q * 4 + 2] = v.z; h[q * 4 + 3] = v.w;
    }
    float acc = bb[0];
#pragma unroll 4
    for (int j = 0; j < 64; j++) {
        float t = ab[j];
#pragma unroll
        for (int i = 0; i < 32; i++) t = fmaf(h[i], aw[i * 64 + j], t);
        acc = fmaf(fmaxf(t, 0.f), bw[j], acc);
    }
    out[n] = acc;
#pragma unroll
    for (int d = 0; d < 3; d++) {
        int idx = NN + n * 3 + d;
        if (idx < out_size) out[idx] = g_coord[n * 3 + d];
    }
}

// ---------------- launch ----------------
extern "C" void kernel_launch(void* const* d_in, const int* in_sizes, int n_in,
                              void* d_out, int out_size) {
    const float* x      = (const float*)d_in[0];
    const void*  ei     = d_in[1];
    const float* ea     = (const float*)d_in[2];
    const float* ci     = (const float*)d_in[3];
    const float* fc1w   = (const float*)d_in[4];
    const float* fc1b   = (const float*)d_in[5];
    const float* k1w    = (const float*)d_in[6];
    const float* k1b    = (const float*)d_in[7];
    const float* k2w    = (const float*)d_in[8];
    const float* k2b    = (const float*)d_in[9];
    const float* k3w    = (const float*)d_in[10];
    const float* k3b    = (const float*)d_in[11];
    const float* cm1w   = (const float*)d_in[12];
    const float* cm1b   = (const float*)d_in[13];
    const float* cm2w   = (const float*)d_in[14];
    const float* cm2b   = (const float*)d_in[15];
    const float* fc2aw  = (const float*)d_in[16];
    const float* fc2ab  = (const float*)d_in[17];
    const float* fc2bw  = (const float*)d_in[18];
    const float* fc2bb  = (const float*)d_in[19];
    float* out = (float*)d_out;

    static int smem_set = 0;
    if (!smem_set) {
        cudaFuncSetAttribute(edge_kernel, cudaFuncAttributeMaxDynamicSharedMemorySize,
                             SMEM_EDGE_FLOATS * 4);
        smem_set = 1;
    }

    detect_kernel<<<1, 32>>>(ei);
    zero_sort_kernel<<<(NN + 255) / 256, 256>>>();
    hist_kernel<<<(EE + 255) / 256, 256>>>(ei);
    scan_kernel<<<1, 1024>>>();
    cntf_kernel<<<(NN + 255) / 256, 256>>>();
    scatter_kernel<<<(EE + 255) / 256, 256>>>(ei);

    coordinit_kernel<<<(NN * 3 + 255) / 256, 256>>>(ci);
    h0_kernel<<<(NN * 32 + 255) / 256, 256>>>(x, fc1w, fc1b);
    k2_mma_kernel<<<dim3(EE / 32, 4), 256>>>(ea, k1w, k1b, k2w, k2b);

    for (int layer = 0; layer < 4; layer++) {
        G_mma_kernel<<<dim3((NN + 63) / 64, 128), 256>>>(k3w);
        bias_zero_kernel<<<(NN * 32 + 255) / 256, 256>>>(k3b);
        edge_kernel<<<NN / NPB, 256, SMEM_EDGE_FLOATS * 4>>>(ei, cm1w, cm1b, cm2w, cm2b);
        node_kernel<<<(NN * 32 + 255) / 256, 256>>>();
    }

    out_kernel<<<(NN + 255) / 256, 256>>>(fc2aw, fc2ab, fc2bw, fc2bb, out, out_size);
}

// round 12
// speedup vs baseline: 1.2416x; 1.0463x over previous
#include <cuda_runtime.h>

#define NN 10000
#define EE 300000
#define NPB 4   // nodes per edge-kernel block

// ---------------- scratch (__device__ globals, no allocs) ----------------
__device__ __align__(16) float g_h[NN * 32];
__device__ __align__(16) float g_k2[(size_t)EE * 256];
__device__ __align__(16) float g_G2[(size_t)NN * 8192];   // [n][c*32+i] node-major
__device__ __align__(16) float g_Bias[NN * 32];
__device__ __align__(16) float g_agg[NN * 32];
__device__ __align__(16) float g_cacc[NN * 3];
__device__ __align__(16) float g_coord[NN * 3];
__device__ float g_cntf[NN];
__device__ int   g_colcnt[NN];
__device__ int   g_rowcnt[NN];
__device__ int   g_cursor[NN];
__device__ int   g_colstart[NN + 1];
__device__ int   g_perm[EE];
__device__ int   g_is64;

// ---------------- tf32 / async helpers ----------------
__device__ __forceinline__ float tf32r(float f) {
    unsigned r;
    asm("cvt.rna.tf32.f32 %0, %1;" : "=r"(r) : "f"(f));
    return __uint_as_float(r);
}

__device__ __forceinline__ void mma_tf32(float* c, const unsigned* a, const unsigned* b) {
    asm volatile(
        "mma.sync.aligned.m16n8k8.row.col.f32.tf32.tf32.f32 "
        "{%0,%1,%2,%3}, {%4,%5,%6,%7}, {%8,%9}, {%0,%1,%2,%3};"
        : "+f"(c[0]), "+f"(c[1]), "+f"(c[2]), "+f"(c[3])
        : "r"(a[0]), "r"(a[1]), "r"(a[2]), "r"(a[3]), "r"(b[0]), "r"(b[1]));
}

__device__ __forceinline__ void cp_async16(void* smem_dst, const void* gmem_src) {
    unsigned s = (unsigned)__cvta_generic_to_shared(smem_dst);
    asm volatile("cp.async.cg.shared.global [%0], [%1], 16;\n" :: "r"(s), "l"(gmem_src));
}
#define CP_COMMIT() asm volatile("cp.async.commit_group;\n" ::)
#define CP_WAIT(N)  asm volatile("cp.async.wait_group %0;\n" :: "n"(N))

// ---------------- edge-index dtype handling ----------------
__global__ void detect_kernel(const void* __restrict__ ei) {
    const int* w = (const int*)ei;
    int lane = threadIdx.x;
    int hi = w[2 * lane + 1];
    unsigned any = __ballot_sync(0xffffffffu, hi != 0);
    if (lane == 0) g_is64 = (any == 0u) ? 1 : 0;
}

__device__ __forceinline__ int eidx(const void* __restrict__ ei, long long pos, int is64) {
    int v = is64 ? (int)((const long long*)ei)[pos] : ((const int*)ei)[pos];
    return min(max(v, 0), NN - 1);
}

// ---------------- small utility kernels ----------------
__global__ void zero_sort_kernel() {
    int i = blockIdx.x * blockDim.x + threadIdx.x;
    if (i < NN) { g_colcnt[i] = 0; g_rowcnt[i] = 0; g_cursor[i] = 0; }
}

__global__ void coordinit_kernel(const float* __restrict__ ci) {
    int i = blockIdx.x * blockDim.x + threadIdx.x;
    if (i < NN * 3) g_coord[i] = ci[i];
}

__global__ void hist_kernel(const void* __restrict__ ei) {
    int e = blockIdx.x * blockDim.x + threadIdx.x;
    int is64 = g_is64;
    if (e < EE) {
        atomicAdd(&g_rowcnt[eidx(ei, e, is64)], 1);
        atomicAdd(&g_colcnt[eidx(ei, (long long)EE + e, is64)], 1);
    }
}

__global__ void cntf_kernel() {
    int n = blockIdx.x * blockDim.x + threadIdx.x;
    if (n < NN) g_cntf[n] = fmaxf(1.f, (float)g_rowcnt[n]);
}

__global__ void scan_kernel() {
    const int BPT = 10;
    int t = threadIdx.x;
    int loc[BPT];
    int s = 0;
#pragma unroll
    for (int j = 0; j < BPT; j++) {
        int b = t * BPT + j;
        int v = (b < NN) ? g_colcnt[b] : 0;
        loc[j] = s; s += v;
    }
    unsigned full = 0xffffffffu;
    int lane = t & 31, wid = t >> 5;
    int v = s;
#pragma unroll
    for (int o = 1; o < 32; o <<= 1) {
        int u = __shfl_up_sync(full, v, o);
        if (lane >= o) v += u;
    }
    __shared__ int wsum[32];
    if (lane == 31) wsum[wid] = v;
    __syncthreads();
    if (wid == 0) {
        int x = wsum[lane];
#pragma unroll
        for (int o = 1; o < 32; o <<= 1) {
            int u = __shfl_up_sync(full, x, o);
            if (lane >= o) x += u;
        }
        wsum[lane] = x;
    }
    __syncthreads();
    int excl = v - s + (wid ? wsum[wid - 1] : 0);
#pragma unroll
    for (int j = 0; j < BPT; j++) {
        int b = t * BPT + j;
        if (b < NN) g_colstart[b] = excl + loc[j];
    }
    if (t == 1023) g_colstart[NN] = wsum[31];
}

__global__ void scatter_kernel(const void* __restrict__ ei) {
    int e = blockIdx.x * blockDim.x + threadIdx.x;
    if (e < EE) {
        int c = eidx(ei, (long long)EE + e, g_is64);
        int p = atomicAdd(&g_cursor[c], 1);
        g_perm[g_colstart[c] + p] = e;
    }
}

// ---------------- model kernels ----------------
__global__ void h0_kernel(const float* __restrict__ x,
                          const float* __restrict__ w, const float* __restrict__ b) {
    int idx = blockIdx.x * blockDim.x + threadIdx.x;
    if (idx >= NN * 32) return;
    int n = idx >> 5, i = idx & 31;
    float acc = b[i];
#pragma unroll
    for (int f = 0; f < 3; f++) acc = fmaf(x[n * 3 + f], w[f * 32 + i], acc);
    g_h[idx] = acc;
}

// k2 = relu(relu(ea@W1+b1)@W2+b2), 3xTF32 mma.
// One block = 32 edges x ALL 256 cols (loop over 4 column chunks):
// t1 + A-splits staged ONCE per K-chunk instead of 4x.
__global__ void __launch_bounds__(256) k2_mma_kernel(
    const float* __restrict__ ea,
    const float* __restrict__ w1, const float* __restrict__ b1,
    const float* __restrict__ w2, const float* __restrict__ b2)
{
    __shared__ union { float t1f[32 * 129]; float kt[32 * 65]; } uk;
    __shared__ float As_b[32 * 36], As_s[32 * 36];
    __shared__ float w2s_b[32 * 72], w2s_s[32 * 72];
    __shared__ float b2s[256];

    int e0 = blockIdx.x * 32;
    int tid = threadIdx.x;

    if (tid < 256) b2s[tid] = b2[tid];
    for (int idx = tid; idx < 32 * 128; idx += 256) {
        int el = idx >> 7, j = idx & 127;
        float acc = b1[j];
#pragma unroll
        for (int f = 0; f < 6; f++) acc = fmaf(ea[(e0 + el) * 6 + f], w1[f * 128 + j], acc);
        uk.t1f[el * 129 + j] = fmaxf(acc, 0.f);
    }

    int w = tid >> 5, lane = tid & 31;
    int g = lane >> 2, tig = lane & 3;
    int wm = w & 1, wn = w >> 1;
    int r0 = wm * 16 + g;

    float acc[4][2][4] = {};

#pragma unroll 1
    for (int kb = 0; kb < 4; kb++) {
        __syncthreads();   // prior readers of As done (or t1f writes visible)
        for (int idx = tid; idx < 1024; idx += 256) {
            int el = idx >> 5, kl = idx & 31;
            float v = uk.t1f[el * 129 + kb * 32 + kl];
            float b = tf32r(v);
            As_b[el * 36 + kl] = b;
            As_s[el * 36 + kl] = tf32r(v - b);
        }
#pragma unroll 1
        for (int n0q = 0; n0q < 4; n0q++) {
            __syncthreads();   // prior w2 readers done; As stores visible (first n0q)
            for (int idx = tid; idx < 2048; idx += 256) {
                int kl = idx >> 6, nl = idx & 63;
                float v = w2[(kb * 32 + kl) * 256 + n0q * 64 + nl];
                float b = tf32r(v);
                w2s_b[kl * 72 + nl] = b;
                w2s_s[kl * 72 + nl] = tf32r(v - b);
            }
            __syncthreads();
#pragma unroll
            for (int ks = 0; ks < 4; ks++) {
                int kk = ks * 8;
                unsigned ab[4], asr[4];
                ab[0]  = __float_as_uint(As_b[r0 * 36 + kk + tig]);
                ab[1]  = __float_as_uint(As_b[(r0 + 8) * 36 + kk + tig]);
                ab[2]  = __float_as_uint(As_b[r0 * 36 + kk + tig + 4]);
                ab[3]  = __float_as_uint(As_b[(r0 + 8) * 36 + kk + tig + 4]);
                asr[0] = __float_as_uint(As_s[r0 * 36 + kk + tig]);
                asr[1] = __float_as_uint(As_s[(r0 + 8) * 36 + kk + tig]);
                asr[2] = __float_as_uint(As_s[r0 * 36 + kk + tig + 4]);
                asr[3] = __float_as_uint(As_s[(r0 + 8) * 36 + kk + tig + 4]);
#pragma unroll
                for (int ni = 0; ni < 2; ni++) {
                    int c0l = wn * 16 + ni * 8 + g;
                    unsigned bb[2], bsr[2];
                    bb[0]  = __float_as_uint(w2s_b[(kk + tig) * 72 + c0l]);
                    bb[1]  = __float_as_uint(w2s_b[(kk + tig + 4) * 72 + c0l]);
                    bsr[0] = __float_as_uint(w2s_s[(kk + tig) * 72 + c0l]);
                    bsr[1] = __float_as_uint(w2s_s[(kk + tig + 4) * 72 + c0l]);
                    mma_tf32(acc[n0q][ni], ab, bb);
                    mma_tf32(acc[n0q][ni], ab, bsr);
                    mma_tf32(acc[n0q][ni], asr, bb);
                }
            }
        }
    }

    // staged coalesced writeout, one column chunk at a time
#pragma unroll 1
    for (int n0q = 0; n0q < 4; n0q++) {
        __syncthreads();
#pragma unroll
        for (int ni = 0; ni < 2; ni++) {
            int col = wn * 16 + ni * 8 + 2 * tig;
            uk.kt[r0 * 65 + col]           = acc[n0q][ni][0];
            uk.kt[r0 * 65 + col + 1]       = acc[n0q][ni][1];
            uk.kt[(r0 + 8) * 65 + col]     = acc[n0q][ni][2];
            uk.kt[(r0 + 8) * 65 + col + 1] = acc[n0q][ni][3];
        }
        __syncthreads();
        for (int idx = tid; idx < 2048; idx += 256) {
            int row = idx >> 6, col = idx & 63;
            float v = fmaxf(uk.kt[row * 65 + col] + b2s[n0q * 64 + col], 0.f);
            g_k2[(size_t)(e0 + row) * 256 + n0q * 64 + col] = v;
        }
    }
}

// G2[n][ci] = sum_j ker3[ci>>5][(ci&31)*32+j] * h[n][j], 3xTF32, node-major.
// One block = 64 nodes x 512 ci (loop 8 chunks): h staged/split once per block.
__global__ void __launch_bounds__(256) G_mma_kernel(const float* __restrict__ k3w) {
    __shared__ float hs_b[64 * 36], hs_s[64 * 36];
    __shared__ float bk_b[32 * 72], bk_s[32 * 72];
    __shared__ float Gt[64 * 65];

    int nn0 = blockIdx.x * 64;
    int ciQ = blockIdx.y * 512;
    int tid = threadIdx.x;

    for (int idx = tid; idx < 64 * 32; idx += 256) {
        int nl = idx >> 5, j = idx & 31;
        int n = nn0 + nl;
        float v = (n < NN) ? g_h[n * 32 + j] : 0.f;
        float b = tf32r(v);
        hs_b[nl * 36 + j] = b;
        hs_s[nl * 36 + j] = tf32r(v - b);
    }

    int w = tid >> 5, lane = tid & 31;
    int g = lane >> 2, tig = lane & 3;
    int wm = w & 1, wn = w >> 1;

#pragma unroll 1
    for (int cq = 0; cq < 8; cq++) {
        int ci0 = ciQ + cq * 64;
        __syncthreads();    // hs visible (first iter); prior bk readers + Gt copy done
        for (int idx = tid; idx < 32 * 64; idx += 256) {
            int cil = idx >> 5, j = idx & 31;
            int ci = ci0 + cil;
            float v = k3w[(size_t)(ci >> 5) * 1024 + (ci & 31) * 32 + j];
            float b = tf32r(v);
            bk_b[j * 72 + cil] = b;
            bk_s[j * 72 + cil] = tf32r(v - b);
        }
        __syncthreads();

        float acc[2][2][4] = {};
#pragma unroll
        for (int ks = 0; ks < 4; ks++) {
            int kk = ks * 8;
            unsigned ab[2][4], asr[2][4], bb[2][2], bsr[2][2];
#pragma unroll
            for (int mi = 0; mi < 2; mi++) {
                int r0 = wm * 32 + mi * 16 + g;
                ab[mi][0]  = __float_as_uint(hs_b[r0 * 36 + kk + tig]);
                ab[mi][1]  = __float_as_uint(hs_b[(r0 + 8) * 36 + kk + tig]);
                ab[mi][2]  = __float_as_uint(hs_b[r0 * 36 + kk + tig + 4]);
                ab[mi][3]  = __float_as_uint(hs_b[(r0 + 8) * 36 + kk + tig + 4]);
                asr[mi][0] = __float_as_uint(hs_s[r0 * 36 + kk + tig]);
                asr[mi][1] = __float_as_uint(hs_s[(r0 + 8) * 36 + kk + tig]);
                asr[mi][2] = __float_as_uint(hs_s[r0 * 36 + kk + tig + 4]);
                asr[mi][3] = __float_as_uint(hs_s[(r0 + 8) * 36 + kk + tig + 4]);
            }
#pragma unroll
            for (int ni = 0; ni < 2; ni++) {
                int c0l = wn * 16 + ni * 8 + g;
                bb[ni][0]  = __float_as_uint(bk_b[(kk + tig) * 72 + c0l]);
                bb[ni][1]  = __float_as_uint(bk_b[(kk + tig + 4) * 72 + c0l]);
                bsr[ni][0] = __float_as_uint(bk_s[(kk + tig) * 72 + c0l]);
                bsr[ni][1] = __float_as_uint(bk_s[(kk + tig + 4) * 72 + c0l]);
            }
#pragma unroll
            for (int mi = 0; mi < 2; mi++)
#pragma unroll
                for (int ni = 0; ni < 2; ni++) {
                    mma_tf32(acc[mi][ni], ab[mi], bb[ni]);
                    mma_tf32(acc[mi][ni], ab[mi], bsr[ni]);
                    mma_tf32(acc[mi][ni], asr[mi], bb[ni]);
                }
        }

        // stage tile, coalesced node-major writeout
#pragma unroll
        for (int mi = 0; mi < 2; mi++) {
            int rl = wm * 32 + mi * 16 + g;
#pragma unroll
            for (int ni = 0; ni < 2; ni++) {
                int cl = wn * 16 + ni * 8 + 2 * tig;
                Gt[rl * 65 + cl]           = acc[mi][ni][0];
                Gt[rl * 65 + cl + 1]       = acc[mi][ni][1];
                Gt[(rl + 8) * 65 + cl]     = acc[mi][ni][2];
                Gt[(rl + 8) * 65 + cl + 1] = acc[mi][ni][3];
            }
        }
        __syncthreads();
        for (int idx = tid; idx < 4096; idx += 256) {
            int row = idx >> 6, col = idx & 63;
            int n = nn0 + row;
            if (n < NN) g_G2[(size_t)n * 8192 + ci0 + col] = Gt[row * 65 + col];
        }
    }
}

// Bias[n][i] = sum_j ker3_b[i*32+j] * h[n][j] (exact fp32); zero agg/cacc.
__global__ void bias_zero_kernel(const float* __restrict__ b3) {
    int idx = blockIdx.x * blockDim.x + threadIdx.x;
    if (idx < NN * 3) g_cacc[idx] = 0.f;
    if (idx >= NN * 32) return;
    int n = idx >> 5, i = idx & 31;
    float acc = 0.f;
#pragma unroll
    for (int j = 0; j < 32; j++) acc = fmaf(b3[i * 32 + j], g_h[n * 32 + j], acc);
    g_Bias[idx] = acc;
    g_agg[idx] = 0.f;
}

// Edge kernel: NPB nodes per block, cp.async double-buffered G2 prefetch.
#define SMEM_EDGE_FLOATS 27080
__global__ void __launch_bounds__(256) edge_kernel(
    const void* __restrict__ ei,
    const float* __restrict__ cm1w, const float* __restrict__ cm1b,
    const float* __restrict__ cm2w, const float* __restrict__ cm2b)
{
    extern __shared__ float sm[];
    float* Gb0   = sm;                  // 8192
    float* Gb1   = sm + 8192;           // 8192
    float* k2s   = sm + 16384;          // 32*260 = 8320
    float* cm1s  = sm + 24704;          // 32*33 = 1056
    float* ms_   = sm + 25760;          // 32*36 = 1152
    float* Bs    = sm + 26912;          // 32
    float* cm1bs = sm + 26944;          // 32
    float* cm2s  = sm + 26976;          // 32
    int*   es    = (int*)(sm + 27008);  // 32
    int*   rs    = (int*)(sm + 27040);  // 32
    float* ccolp = sm + 27072;          // [0..2]=ccol, [3]=cm2b0

    int tid = threadIdx.x, w = tid >> 5, lane = tid & 31;
    int is64 = g_is64;
    int n0 = blockIdx.x * NPB;

    for (int idx = tid; idx < 1024; idx += 256)
        cm1s[(idx >> 5) * 33 + (idx & 31)] = cm1w[idx];
    if (tid < 32) { cm1bs[tid] = cm1b[tid]; cm2s[tid] = cm2w[tid]; }
    if (tid == 0) ccolp[3] = cm2b[0];

    {
        const float* src = g_G2 + (size_t)n0 * 8192;
        for (int idx = tid; idx < 2048; idx += 256)
            cp_async16(Gb0 + idx * 4, src + idx * 4);
        CP_COMMIT();
    }

    int lg = lane >> 3;
    int iq = lane & 7;
    const unsigned full = 0xffffffffu;

#pragma unroll 1
    for (int t = 0; t < NPB; t++) {
        int n = n0 + t;
        float* G2s = (t & 1) ? Gb1 : Gb0;
        if (t + 1 < NPB) {
            float* nxt = (t & 1) ? Gb0 : Gb1;
            const float* src = g_G2 + (size_t)(n + 1) * 8192;
            for (int idx = tid; idx < 2048; idx += 256)
                cp_async16(nxt + idx * 4, src + idx * 4);
            CP_COMMIT();
            CP_WAIT(1);
        } else {
            CP_WAIT(0);
        }
        if (tid < 32) Bs[tid] = g_Bias[n * 32 + tid];
        if (tid < 3) ccolp[tid] = g_coord[n * 3 + tid];
        __syncthreads();

        int cs0 = g_colstart[n];
        int deg = g_colstart[n + 1] - cs0;

        for (int base = 0; base < deg; base += 32) {
            if (base) __syncthreads();
            if (tid < 32) {
                int p = base + tid;
                int e = (p < deg) ? g_perm[cs0 + p] : -1;
                es[tid] = e;
                rs[tid] = (e >= 0) ? eidx(ei, e, is64) : 0;
            }
            __syncthreads();
            for (int idx = tid; idx < 2048; idx += 256) {
                int el = idx >> 6, c4 = idx & 63;
                int e = es[el];
                float4 v = (e >= 0) ? ((const float4*)g_k2)[(size_t)e * 64 + c4]
                                    : make_float4(0.f, 0.f, 0.f, 0.f);
                *(float4*)&k2s[el * 260 + c4 * 4] = v;
            }
            __syncthreads();

            int e_l0 = w * 4;
            float acc[4][4] = {};
            const float4* G4 = (const float4*)G2s;
#pragma unroll 4
            for (int cb = 0; cb < 64; cb++) {
                int c = cb * 4 + lg;
                float4 gv = G4[c * 8 + iq];
                float k0 = k2s[(e_l0 + 0) * 260 + c];
                float k1 = k2s[(e_l0 + 1) * 260 + c];
                float k2v = k2s[(e_l0 + 2) * 260 + c];
                float k3 = k2s[(e_l0 + 3) * 260 + c];
                acc[0][0] = fmaf(k0, gv.x, acc[0][0]); acc[0][1] = fmaf(k0, gv.y, acc[0][1]);
                acc[0][2] = fmaf(k0, gv.z, acc[0][2]); acc[0][3] = fmaf(k0, gv.w, acc[0][3]);
                acc[1][0] = fmaf(k1, gv.x, acc[1][0]); acc[1][1] = fmaf(k1, gv.y, acc[1][1]);
                acc[1][2] = fmaf(k1, gv.z, acc[1][2]); acc[1][3] = fmaf(k1, gv.w, acc[1][3]);
                acc[2][0] = fmaf(k2v, gv.x, acc[2][0]); acc[2][1] = fmaf(k2v, gv.y, acc[2][1]);
                acc[2][2] = fmaf(k2v, gv.z, acc[2][2]); acc[2][3] = fmaf(k2v, gv.w, acc[2][3]);
                acc[3][0] = fmaf(k3, gv.x, acc[3][0]); acc[3][1] = fmaf(k3, gv.y, acc[3][1]);
                acc[3][2] = fmaf(k3, gv.z, acc[3][2]); acc[3][3] = fmaf(k3, gv.w, acc[3][3]);
            }
#pragma unroll
            for (int q = 0; q < 4; q++)
#pragma unroll
                for (int c = 0; c < 4; c++) {
                    acc[q][c] += __shfl_xor_sync(full, acc[q][c], 8);
                    acc[q][c] += __shfl_xor_sync(full, acc[q][c], 16);
                }
            if (lane < 8) {
#pragma unroll
                for (int q = 0; q < 4; q++)
                    *(float4*)&ms_[(e_l0 + q) * 36 + iq * 4] =
                        make_float4(acc[q][0], acc[q][1], acc[q][2], acc[q][3]);
            }
            __syncwarp();
#pragma unroll
            for (int q = 0; q < 4; q++) {
                int el = e_l0 + q;
                float mf = ms_[el * 36 + lane] + Bs[lane];
                ms_[el * 36 + lane] = mf;
                if (es[el] >= 0) atomicAdd(&g_agg[rs[el] * 32 + lane], mf);
            }
            __syncwarp();
#pragma unroll 1
            for (int q = 0; q < 4; q++) {
                int el = e_l0 + q;
                float tt = cm1bs[lane];
#pragma unroll
                for (int i = 0; i < 32; i++)
                    tt = fmaf(ms_[el * 36 + i], cm1s[i * 33 + lane], tt);
                tt = fmaxf(tt, 0.f) * cm2s[lane];
#pragma unroll
                for (int off = 16; off; off >>= 1) tt += __shfl_xor_sync(full, tt, off);
                int e = es[el];
                if (e >= 0 && lane < 3) {
                    float we = tt + ccolp[3];
                    int r = rs[el];
                    atomicAdd(&g_cacc[r * 3 + lane], (g_coord[r * 3 + lane] - ccolp[lane]) * we);
                }
            }
        }
        __syncthreads();
    }
}

__global__ void node_kernel() {
    int idx = blockIdx.x * blockDim.x + threadIdx.x;
    if (idx >= NN * 32) return;
    int n = idx >> 5, i = idx & 31;
    float cf = g_cntf[n];
    float hv = g_h[idx] + g_agg[idx] / cf;
    g_h[idx] = fmaxf(hv, 0.f);
    if (i < 3) g_coord[n * 3 + i] += g_cacc[n * 3 + i] / cf;
}

__global__ void out_kernel(const float* __restrict__ aw, const float* __restrict__ ab,
                           const float* __restrict__ bw, const float* __restrict__ bb,
                           float* __restrict__ out, int out_size) {
    int n = blockIdx.x * blockDim.x + threadIdx.x;
    if (n >= NN) return;
    float h[32];
    const float4* hp = (const float4*)(g_h + n * 32);
#pragma unroll
    for (int q = 0; q < 8; q++) {
        float4 v = hp[q];
        h[q * 4] = v.x; h[q * 4 + 1] = v.y; h[q * 4 + 2] = v.z; h[q * 4 + 3] = v.w;
    }
    float acc = bb[0];
#pragma unroll 4
    for (int j = 0; j < 64; j++) {
        float t = ab[j];
#pragma unroll
        for (int i = 0; i < 32; i++) t = fmaf(h[i], aw[i * 64 + j], t);
        acc = fmaf(fmaxf(t, 0.f), bw[j], acc);
    }
    out[n] = acc;
#pragma unroll
    for (int d = 0; d < 3; d++) {
        int idx = NN + n * 3 + d;
        if (idx < out_size) out[idx] = g_coord[n * 3 + d];
    }
}

// ---------------- launch ----------------
extern "C" void kernel_launch(void* const* d_in, const int* in_sizes, int n_in,
                              void* d_out, int out_size) {
    const float* x      = (const float*)d_in[0];
    const void*  ei     = d_in[1];
    const float* ea     = (const float*)d_in[2];
    const float* ci     = (const float*)d_in[3];
    const float* fc1w   = (const float*)d_in[4];
    const float* fc1b   = (const float*)d_in[5];
    const float* k1w    = (const float*)d_in[6];
    const float* k1b    = (const float*)d_in[7];
    const float* k2w    = (const float*)d_in[8];
    const float* k2b    = (const float*)d_in[9];
    const float* k3w    = (const float*)d_in[10];
    const float* k3b    = (const float*)d_in[11];
    const float* cm1w   = (const float*)d_in[12];
    const float* cm1b   = (const float*)d_in[13];
    const float* cm2w   = (const float*)d_in[14];
    const float* cm2b   = (const float*)d_in[15];
    const float* fc2aw  = (const float*)d_in[16];
    const float* fc2ab  = (const float*)d_in[17];
    const float* fc2bw  = (const float*)d_in[18];
    const float* fc2bb  = (const float*)d_in[19];
    float* out = (float*)d_out;

    cudaFuncSetAttribute(edge_kernel, cudaFuncAttributeMaxDynamicSharedMemorySize,
                         SMEM_EDGE_FLOATS * 4);

    // Launch order: k2_mma placed 4th so the ncu capture window (-s 5 -c 1,
    // with ~2 harness-internal launches first) lands on it.
    detect_kernel<<<1, 32>>>(ei);
    zero_sort_kernel<<<(NN + 255) / 256, 256>>>();
    hist_kernel<<<(EE + 255) / 256, 256>>>(ei);
    k2_mma_kernel<<<EE / 32, 256>>>(ea, k1w, k1b, k2w, k2b);
    scan_kernel<<<1, 1024>>>();
    cntf_kernel<<<(NN + 255) / 256, 256>>>();
    scatter_kernel<<<(EE + 255) / 256, 256>>>(ei);
    coordinit_kernel<<<(NN * 3 + 255) / 256, 256>>>(ci);
    h0_kernel<<<(NN * 32 + 255) / 256, 256>>>(x, fc1w, fc1b);

    for (int layer = 0; layer < 4; layer++) {
        G_mma_kernel<<<dim3((NN + 63) / 64, 16), 256>>>(k3w);
        bias_zero_kernel<<<(NN * 32 + 255) / 256, 256>>>(k3b);
        edge_kernel<<<NN / NPB, 256, SMEM_EDGE_FLOATS * 4>>>(ei, cm1w, cm1b, cm2w, cm2b);
        node_kernel<<<(NN * 32 + 255) / 256, 256>>>();
    }

    out_kernel<<<(NN + 255) / 256, 256>>>(fc2aw, fc2ab, fc2bw, fc2bb, out, out_size);
}

// round 13
// speedup vs baseline: 1.3413x; 1.0803x over previous
#include <cuda_runtime.h>

#define NN 10000
#define EE 300000
#define NPB 4   // nodes per edge-kernel block

// ---------------- scratch (__device__ globals, no allocs) ----------------
__device__ __align__(16) float g_h[NN * 32];
__device__ __align__(16) float g_k2[(size_t)EE * 256];
__device__ __align__(16) float g_G2[(size_t)NN * 8192];   // [n][c*32+i] node-major
__device__ __align__(16) float g_Bias[NN * 32];
__device__ __align__(16) float g_agg[NN * 32];
__device__ __align__(16) float g_cacc[NN * 3];
__device__ __align__(16) float g_coord[NN * 3];
__device__ __align__(16) float g_w2b[128 * 256];
__device__ __align__(16) float g_w2s[128 * 256];
__device__ float g_cntf[NN];
__device__ int   g_colcnt[NN];
__device__ int   g_rowcnt[NN];
__device__ int   g_cursor[NN];
__device__ int   g_colstart[NN + 1];
__device__ int   g_perm[EE];
__device__ int   g_is64;

// ---------------- tf32 / async helpers ----------------
__device__ __forceinline__ float tf32r(float f) {
    unsigned r;
    asm("cvt.rna.tf32.f32 %0, %1;" : "=r"(r) : "f"(f));
    return __uint_as_float(r);
}

__device__ __forceinline__ void mma_tf32(float* c, const unsigned* a, const unsigned* b) {
    asm volatile(
        "mma.sync.aligned.m16n8k8.row.col.f32.tf32.tf32.f32 "
        "{%0,%1,%2,%3}, {%4,%5,%6,%7}, {%8,%9}, {%0,%1,%2,%3};"
        : "+f"(c[0]), "+f"(c[1]), "+f"(c[2]), "+f"(c[3])
        : "r"(a[0]), "r"(a[1]), "r"(a[2]), "r"(a[3]), "r"(b[0]), "r"(b[1]));
}

__device__ __forceinline__ void cp_async16(void* smem_dst, const void* gmem_src) {
    unsigned s = (unsigned)__cvta_generic_to_shared(smem_dst);
    asm volatile("cp.async.cg.shared.global [%0], [%1], 16;\n" :: "r"(s), "l"(gmem_src));
}
#define CP_COMMIT() asm volatile("cp.async.commit_group;\n" ::)
#define CP_WAIT(N)  asm volatile("cp.async.wait_group %0;\n" :: "n"(N))

// ---------------- edge-index dtype handling ----------------
__global__ void detect_kernel(const void* __restrict__ ei) {
    const int* w = (const int*)ei;
    int lane = threadIdx.x;
    int hi = w[2 * lane + 1];
    unsigned any = __ballot_sync(0xffffffffu, hi != 0);
    if (lane == 0) g_is64 = (any == 0u) ? 1 : 0;
}

__device__ __forceinline__ int eidx(const void* __restrict__ ei, long long pos, int is64) {
    int v = is64 ? (int)((const long long*)ei)[pos] : ((const int*)ei)[pos];
    return min(max(v, 0), NN - 1);
}

// ---------------- small utility kernels ----------------
__global__ void zero_sort_kernel() {
    int i = blockIdx.x * blockDim.x + threadIdx.x;
    if (i < NN) { g_colcnt[i] = 0; g_rowcnt[i] = 0; g_cursor[i] = 0; }
}

__global__ void coordinit_kernel(const float* __restrict__ ci) {
    int i = blockIdx.x * blockDim.x + threadIdx.x;
    if (i < NN * 3) g_coord[i] = ci[i];
}

__global__ void hist_kernel(const void* __restrict__ ei) {
    int e = blockIdx.x * blockDim.x + threadIdx.x;
    int is64 = g_is64;
    if (e < EE) {
        atomicAdd(&g_rowcnt[eidx(ei, e, is64)], 1);
        atomicAdd(&g_colcnt[eidx(ei, (long long)EE + e, is64)], 1);
    }
}

__global__ void cntf_kernel() {
    int n = blockIdx.x * blockDim.x + threadIdx.x;
    if (n < NN) g_cntf[n] = fmaxf(1.f, (float)g_rowcnt[n]);
}

__global__ void scan_kernel() {
    const int BPT = 10;
    int t = threadIdx.x;
    int loc[BPT];
    int s = 0;
#pragma unroll
    for (int j = 0; j < BPT; j++) {
        int b = t * BPT + j;
        int v = (b < NN) ? g_colcnt[b] : 0;
        loc[j] = s; s += v;
    }
    unsigned full = 0xffffffffu;
    int lane = t & 31, wid = t >> 5;
    int v = s;
#pragma unroll
    for (int o = 1; o < 32; o <<= 1) {
        int u = __shfl_up_sync(full, v, o);
        if (lane >= o) v += u;
    }
    __shared__ int wsum[32];
    if (lane == 31) wsum[wid] = v;
    __syncthreads();
    if (wid == 0) {
        int x = wsum[lane];
#pragma unroll
        for (int o = 1; o < 32; o <<= 1) {
            int u = __shfl_up_sync(full, x, o);
            if (lane >= o) x += u;
        }
        wsum[lane] = x;
    }
    __syncthreads();
    int excl = v - s + (wid ? wsum[wid - 1] : 0);
#pragma unroll
    for (int j = 0; j < BPT; j++) {
        int b = t * BPT + j;
        if (b < NN) g_colstart[b] = excl + loc[j];
    }
    if (t == 1023) g_colstart[NN] = wsum[31];
}

__global__ void scatter_kernel(const void* __restrict__ ei) {
    int e = blockIdx.x * blockDim.x + threadIdx.x;
    if (e < EE) {
        int c = eidx(ei, (long long)EE + e, g_is64);
        int p = atomicAdd(&g_cursor[c], 1);
        g_perm[g_colstart[c] + p] = e;
    }
}

// ---------------- model kernels ----------------
__global__ void h0_kernel(const float* __restrict__ x,
                          const float* __restrict__ w, const float* __restrict__ b) {
    int idx = blockIdx.x * blockDim.x + threadIdx.x;
    if (idx >= NN * 32) return;
    int n = idx >> 5, i = idx & 31;
    float acc = b[i];
#pragma unroll
    for (int f = 0; f < 3; f++) acc = fmaf(x[n * 3 + f], w[f * 32 + i], acc);
    g_h[idx] = acc;
}

// Precompute tf32 splits of W2 once.
__global__ void w2split_kernel(const float* __restrict__ w2) {
    int i = blockIdx.x * blockDim.x + threadIdx.x;
    if (i < 128 * 256) {
        float v = w2[i];
        float b = tf32r(v);
        g_w2b[i] = b;
        g_w2s[i] = tf32r(v - b);
    }
}

// k2 v3: 32 edges x 256 cols per block; warp tile 32x32; K-chunks of 16.
// W2 splits cp.async'd from precomputed global; frag LDS halved vs v2.
// smem layout (floats): [0,8448) w2b_s(16*264)+w2s_s(16*264) (union: kt 32*260)
//                       [8448,9088) As_b(32*20)  [9088,9728) As_s
//                       [9728,13856) t1f(32*129) [13856,14112) b2s
#define K2_SMEM_FLOATS 14112
__global__ void __launch_bounds__(256) k2_mma_kernel(
    const float* __restrict__ ea,
    const float* __restrict__ w1, const float* __restrict__ b1,
    const float* __restrict__ b2)
{
    extern __shared__ float sk[];
    float* w2b_s = sk;            // 16*264
    float* w2s_s = sk + 4224;     // 16*264
    float* kt    = sk;            // 32*260 (reuses w2 region after MMA)
    float* As_b  = sk + 8448;     // 32*20
    float* As_s  = sk + 9088;     // 32*20
    float* t1f   = sk + 9728;     // 32*129
    float* b2s   = sk + 13856;    // 256

    int e0 = blockIdx.x * 32;
    int tid = threadIdx.x;

    if (tid < 256) b2s[tid] = b2[tid];
    // t1 fp32 (exact)
    for (int idx = tid; idx < 32 * 128; idx += 256) {
        int el = idx >> 7, j = idx & 127;
        float acc = b1[j];
#pragma unroll
        for (int f = 0; f < 6; f++) acc = fmaf(ea[(e0 + el) * 6 + f], w1[f * 128 + j], acc);
        t1f[el * 129 + j] = fmaxf(acc, 0.f);
    }

    int w = tid >> 5, lane = tid & 31;
    int g = lane >> 2, tig = lane & 3;
    int wn = w;               // warp covers cols [w*32, w*32+32)

    float acc[2][4][4] = {};  // mi (rows 0-15/16-31), ni (8-col groups), frag

#pragma unroll 1
    for (int kb = 0; kb < 8; kb++) {
        __syncthreads();   // prior readers done; t1f writes visible (first iter)
        // stage W2 split chunk (16 k-rows x 256 cols) via cp.async
        for (int idx = tid; idx < 1024; idx += 256) {
            int r = idx >> 6, q = idx & 63;
            cp_async16(w2b_s + r * 264 + q * 4, g_w2b + (kb * 16 + r) * 256 + q * 4);
            cp_async16(w2s_s + r * 264 + q * 4, g_w2s + (kb * 16 + r) * 256 + q * 4);
        }
        CP_COMMIT();
        // stage A splits (32 edges x 16 k)
        for (int idx = tid; idx < 512; idx += 256) {
            int el = idx >> 4, kl = idx & 15;
            float v = t1f[el * 129 + kb * 16 + kl];
            float b = tf32r(v);
            As_b[el * 20 + kl] = b;
            As_s[el * 20 + kl] = tf32r(v - b);
        }
        CP_WAIT(0);
        __syncthreads();

#pragma unroll
        for (int ks = 0; ks < 2; ks++) {
            int kk = ks * 8;
            unsigned ab[2][4], asr[2][4];
#pragma unroll
            for (int mi = 0; mi < 2; mi++) {
                int r0 = mi * 16;
                ab[mi][0]  = __float_as_uint(As_b[(r0 + g) * 20 + kk + tig]);
                ab[mi][1]  = __float_as_uint(As_b[(r0 + g + 8) * 20 + kk + tig]);
                ab[mi][2]  = __float_as_uint(As_b[(r0 + g) * 20 + kk + tig + 4]);
                ab[mi][3]  = __float_as_uint(As_b[(r0 + g + 8) * 20 + kk + tig + 4]);
                asr[mi][0] = __float_as_uint(As_s[(r0 + g) * 20 + kk + tig]);
                asr[mi][1] = __float_as_uint(As_s[(r0 + g + 8) * 20 + kk + tig]);
                asr[mi][2] = __float_as_uint(As_s[(r0 + g) * 20 + kk + tig + 4]);
                asr[mi][3] = __float_as_uint(As_s[(r0 + g + 8) * 20 + kk + tig + 4]);
            }
            unsigned bb[4][2], bsr[4][2];
#pragma unroll
            for (int ni = 0; ni < 4; ni++) {
                int c0l = wn * 32 + ni * 8 + g;
                bb[ni][0]  = __float_as_uint(w2b_s[(kk + tig) * 264 + c0l]);
                bb[ni][1]  = __float_as_uint(w2b_s[(kk + tig + 4) * 264 + c0l]);
                bsr[ni][0] = __float_as_uint(w2s_s[(kk + tig) * 264 + c0l]);
                bsr[ni][1] = __float_as_uint(w2s_s[(kk + tig + 4) * 264 + c0l]);
            }
#pragma unroll
            for (int mi = 0; mi < 2; mi++)
#pragma unroll
                for (int ni = 0; ni < 4; ni++) {
                    mma_tf32(acc[mi][ni], ab[mi], bb[ni]);
                    mma_tf32(acc[mi][ni], ab[mi], bsr[ni]);
                    mma_tf32(acc[mi][ni], asr[mi], bb[ni]);
                }
        }
    }

    // stage output tile (reuse w2 smem region), coalesced writeout
    __syncthreads();
#pragma unroll
    for (int mi = 0; mi < 2; mi++) {
        int r = mi * 16 + g;
#pragma unroll
        for (int ni = 0; ni < 4; ni++) {
            int col = wn * 32 + ni * 8 + 2 * tig;
            kt[r * 260 + col]           = acc[mi][ni][0];
            kt[r * 260 + col + 1]       = acc[mi][ni][1];
            kt[(r + 8) * 260 + col]     = acc[mi][ni][2];
            kt[(r + 8) * 260 + col + 1] = acc[mi][ni][3];
        }
    }
    __syncthreads();
    for (int idx = tid; idx < 8192; idx += 256) {
        int row = idx >> 8, col = idx & 255;
        float v = fmaxf(kt[row * 260 + col] + b2s[col], 0.f);
        g_k2[(size_t)(e0 + row) * 256 + col] = v;
    }
}

// G2[n][ci] = sum_j ker3[ci>>5][(ci&31)*32+j] * h[n][j], 3xTF32, node-major.
__global__ void __launch_bounds__(256) G_mma_kernel(const float* __restrict__ k3w) {
    __shared__ float hs_b[64 * 36], hs_s[64 * 36];
    __shared__ float bk_b[32 * 72], bk_s[32 * 72];
    __shared__ float Gt[64 * 65];

    int nn0 = blockIdx.x * 64;
    int ciQ = blockIdx.y * 512;
    int tid = threadIdx.x;

    for (int idx = tid; idx < 64 * 32; idx += 256) {
        int nl = idx >> 5, j = idx & 31;
        int n = nn0 + nl;
        float v = (n < NN) ? g_h[n * 32 + j] : 0.f;
        float b = tf32r(v);
        hs_b[nl * 36 + j] = b;
        hs_s[nl * 36 + j] = tf32r(v - b);
    }

    int w = tid >> 5, lane = tid & 31;
    int g = lane >> 2, tig = lane & 3;
    int wm = w & 1, wn = w >> 1;

#pragma unroll 1
    for (int cq = 0; cq < 8; cq++) {
        int ci0 = ciQ + cq * 64;
        __syncthreads();
        for (int idx = tid; idx < 32 * 64; idx += 256) {
            int cil = idx >> 5, j = idx & 31;
            int ci = ci0 + cil;
            float v = k3w[(size_t)(ci >> 5) * 1024 + (ci & 31) * 32 + j];
            float b = tf32r(v);
            bk_b[j * 72 + cil] = b;
            bk_s[j * 72 + cil] = tf32r(v - b);
        }
        __syncthreads();

        float acc[2][2][4] = {};
#pragma unroll
        for (int ks = 0; ks < 4; ks++) {
            int kk = ks * 8;
            unsigned ab[2][4], asr[2][4], bb[2][2], bsr[2][2];
#pragma unroll
            for (int mi = 0; mi < 2; mi++) {
                int r0 = wm * 32 + mi * 16 + g;
                ab[mi][0]  = __float_as_uint(hs_b[r0 * 36 + kk + tig]);
                ab[mi][1]  = __float_as_uint(hs_b[(r0 + 8) * 36 + kk + tig]);
                ab[mi][2]  = __float_as_uint(hs_b[r0 * 36 + kk + tig + 4]);
                ab[mi][3]  = __float_as_uint(hs_b[(r0 + 8) * 36 + kk + tig + 4]);
                asr[mi][0] = __float_as_uint(hs_s[r0 * 36 + kk + tig]);
                asr[mi][1] = __float_as_uint(hs_s[(r0 + 8) * 36 + kk + tig]);
                asr[mi][2] = __float_as_uint(hs_s[r0 * 36 + kk + tig + 4]);
                asr[mi][3] = __float_as_uint(hs_s[(r0 + 8) * 36 + kk + tig + 4]);
            }
#pragma unroll
            for (int ni = 0; ni < 2; ni++) {
                int c0l = wn * 16 + ni * 8 + g;
                bb[ni][0]  = __float_as_uint(bk_b[(kk + tig) * 72 + c0l]);
                bb[ni][1]  = __float_as_uint(bk_b[(kk + tig + 4) * 72 + c0l]);
                bsr[ni][0] = __float_as_uint(bk_s[(kk + tig) * 72 + c0l]);
                bsr[ni][1] = __float_as_uint(bk_s[(kk + tig + 4) * 72 + c0l]);
            }
#pragma unroll
            for (int mi = 0; mi < 2; mi++)
#pragma unroll
                for (int ni = 0; ni < 2; ni++) {
                    mma_tf32(acc[mi][ni], ab[mi], bb[ni]);
                    mma_tf32(acc[mi][ni], ab[mi], bsr[ni]);
                    mma_tf32(acc[mi][ni], asr[mi], bb[ni]);
                }
        }

#pragma unroll
        for (int mi = 0; mi < 2; mi++) {
            int rl = wm * 32 + mi * 16 + g;
#pragma unroll
            for (int ni = 0; ni < 2; ni++) {
                int cl = wn * 16 + ni * 8 + 2 * tig;
                Gt[rl * 65 + cl]           = acc[mi][ni][0];
                Gt[rl * 65 + cl + 1]       = acc[mi][ni][1];
                Gt[(rl + 8) * 65 + cl]     = acc[mi][ni][2];
                Gt[(rl + 8) * 65 + cl + 1] = acc[mi][ni][3];
            }
        }
        __syncthreads();
        for (int idx = tid; idx < 4096; idx += 256) {
            int row = idx >> 6, col = idx & 63;
            int n = nn0 + row;
            if (n < NN) g_G2[(size_t)n * 8192 + ci0 + col] = Gt[row * 65 + col];
        }
    }
}

// Bias[n][i] = sum_j ker3_b[i*32+j] * h[n][j] (exact fp32); zero agg/cacc.
__global__ void bias_zero_kernel(const float* __restrict__ b3) {
    int idx = blockIdx.x * blockDim.x + threadIdx.x;
    if (idx < NN * 3) g_cacc[idx] = 0.f;
    if (idx >= NN * 32) return;
    int n = idx >> 5, i = idx & 31;
    float acc = 0.f;
#pragma unroll
    for (int j = 0; j < 32; j++) acc = fmaf(b3[i * 32 + j], g_h[n * 32 + j], acc);
    g_Bias[idx] = acc;
    g_agg[idx] = 0.f;
}

// Edge kernel: NPB nodes per block, cp.async double-buffered G2 prefetch.
#define SMEM_EDGE_FLOATS 27080
__global__ void __launch_bounds__(256) edge_kernel(
    const void* __restrict__ ei,
    const float* __restrict__ cm1w, const float* __restrict__ cm1b,
    const float* __restrict__ cm2w, const float* __restrict__ cm2b)
{
    extern __shared__ float sm[];
    float* Gb0   = sm;                  // 8192
    float* Gb1   = sm + 8192;           // 8192
    float* k2s   = sm + 16384;          // 32*260 = 8320
    float* cm1s  = sm + 24704;          // 32*33 = 1056
    float* ms_   = sm + 25760;          // 32*36 = 1152
    float* Bs    = sm + 26912;          // 32
    float* cm1bs = sm + 26944;          // 32
    float* cm2s  = sm + 26976;          // 32
    int*   es    = (int*)(sm + 27008);  // 32
    int*   rs    = (int*)(sm + 27040);  // 32
    float* ccolp = sm + 27072;          // [0..2]=ccol, [3]=cm2b0

    int tid = threadIdx.x, w = tid >> 5, lane = tid & 31;
    int is64 = g_is64;
    int n0 = blockIdx.x * NPB;

    for (int idx = tid; idx < 1024; idx += 256)
        cm1s[(idx >> 5) * 33 + (idx & 31)] = cm1w[idx];
    if (tid < 32) { cm1bs[tid] = cm1b[tid]; cm2s[tid] = cm2w[tid]; }
    if (tid == 0) ccolp[3] = cm2b[0];

    {
        const float* src = g_G2 + (size_t)n0 * 8192;
        for (int idx = tid; idx < 2048; idx += 256)
            cp_async16(Gb0 + idx * 4, src + idx * 4);
        CP_COMMIT();
    }

    int lg = lane >> 3;
    int iq = lane & 7;
    const unsigned full = 0xffffffffu;

#pragma unroll 1
    for (int t = 0; t < NPB; t++) {
        int n = n0 + t;
        float* G2s = (t & 1) ? Gb1 : Gb0;
        if (t + 1 < NPB) {
            float* nxt = (t & 1) ? Gb0 : Gb1;
            const float* src = g_G2 + (size_t)(n + 1) * 8192;
            for (int idx = tid; idx < 2048; idx += 256)
                cp_async16(nxt + idx * 4, src + idx * 4);
            CP_COMMIT();
            CP_WAIT(1);
        } else {
            CP_WAIT(0);
        }
        if (tid < 32) Bs[tid] = g_Bias[n * 32 + tid];
        if (tid < 3) ccolp[tid] = g_coord[n * 3 + tid];
        __syncthreads();

        int cs0 = g_colstart[n];
        int deg = g_colstart[n + 1] - cs0;

        for (int base = 0; base < deg; base += 32) {
            if (base) __syncthreads();
            if (tid < 32) {
                int p = base + tid;
                int e = (p < deg) ? g_perm[cs0 + p] : -1;
                es[tid] = e;
                rs[tid] = (e >= 0) ? eidx(ei, e, is64) : 0;
            }
            __syncthreads();
            for (int idx = tid; idx < 2048; idx += 256) {
                int el = idx >> 6, c4 = idx & 63;
                int e = es[el];
                float4 v = (e >= 0) ? ((const float4*)g_k2)[(size_t)e * 64 + c4]
                                    : make_float4(0.f, 0.f, 0.f, 0.f);
                *(float4*)&k2s[el * 260 + c4 * 4] = v;
            }
            __syncthreads();

            int e_l0 = w * 4;
            float acc[4][4] = {};
            const float4* G4 = (const float4*)G2s;
#pragma unroll 4
            for (int cb = 0; cb < 64; cb++) {
                int c = cb * 4 + lg;
                float4 gv = G4[c * 8 + iq];
                float k0 = k2s[(e_l0 + 0) * 260 + c];
                float k1 = k2s[(e_l0 + 1) * 260 + c];
                float k2v = k2s[(e_l0 + 2) * 260 + c];
                float k3 = k2s[(e_l0 + 3) * 260 + c];
                acc[0][0] = fmaf(k0, gv.x, acc[0][0]); acc[0][1] = fmaf(k0, gv.y, acc[0][1]);
                acc[0][2] = fmaf(k0, gv.z, acc[0][2]); acc[0][3] = fmaf(k0, gv.w, acc[0][3]);
                acc[1][0] = fmaf(k1, gv.x, acc[1][0]); acc[1][1] = fmaf(k1, gv.y, acc[1][1]);
                acc[1][2] = fmaf(k1, gv.z, acc[1][2]); acc[1][3] = fmaf(k1, gv.w, acc[1][3]);
                acc[2][0] = fmaf(k2v, gv.x, acc[2][0]); acc[2][1] = fmaf(k2v, gv.y, acc[2][1]);
                acc[2][2] = fmaf(k2v, gv.z, acc[2][2]); acc[2][3] = fmaf(k2v, gv.w, acc[2][3]);
                acc[3][0] = fmaf(k3, gv.x, acc[3][0]); acc[3][1] = fmaf(k3, gv.y, acc[3][1]);
                acc[3][2] = fmaf(k3, gv.z, acc[3][2]); acc[3][3] = fmaf(k3, gv.w, acc[3][3]);
            }
#pragma unroll
            for (int q = 0; q < 4; q++)
#pragma unroll
                for (int c = 0; c < 4; c++) {
                    acc[q][c] += __shfl_xor_sync(full, acc[q][c], 8);
                    acc[q][c] += __shfl_xor_sync(full, acc[q][c], 16);
                }
            if (lane < 8) {
#pragma unroll
                for (int q = 0; q < 4; q++)
                    *(float4*)&ms_[(e_l0 + q) * 36 + iq * 4] =
                        make_float4(acc[q][0], acc[q][1], acc[q][2], acc[q][3]);
            }
            __syncwarp();
#pragma unroll
            for (int q = 0; q < 4; q++) {
                int el = e_l0 + q;
                float mf = ms_[el * 36 + lane] + Bs[lane];
                ms_[el * 36 + lane] = mf;
                if (es[el] >= 0) atomicAdd(&g_agg[rs[el] * 32 + lane], mf);
            }
            __syncwarp();
#pragma unroll 1
            for (int q = 0; q < 4; q++) {
                int el = e_l0 + q;
                float tt = cm1bs[lane];
#pragma unroll
                for (int i = 0; i < 32; i++)
                    tt = fmaf(ms_[el * 36 + i], cm1s[i * 33 + lane], tt);
                tt = fmaxf(tt, 0.f) * cm2s[lane];
#pragma unroll
                for (int off = 16; off; off >>= 1) tt += __shfl_xor_sync(full, tt, off);
                int e = es[el];
                if (e >= 0 && lane < 3) {
                    float we = tt + ccolp[3];
                    int r = rs[el];
                    atomicAdd(&g_cacc[r * 3 + lane], (g_coord[r * 3 + lane] - ccolp[lane]) * we);
                }
            }
        }
        __syncthreads();
    }
}

__global__ void node_kernel() {
    int idx = blockIdx.x * blockDim.x + threadIdx.x;
    if (idx >= NN * 32) return;
    int n = idx >> 5, i = idx & 31;
    float cf = g_cntf[n];
    float hv = g_h[idx] + g_agg[idx] / cf;
    g_h[idx] = fmaxf(hv, 0.f);
    if (i < 3) g_coord[n * 3 + i] += g_cacc[n * 3 + i] / cf;
}

__global__ void out_kernel(const float* __restrict__ aw, const float* __restrict__ ab,
                           const float* __restrict__ bw, const float* __restrict__ bb,
                           float* __restrict__ out, int out_size) {
    int n = blockIdx.x * blockDim.x + threadIdx.x;
    if (n >= NN) return;
    float h[32];
    const float4* hp = (const float4*)(g_h + n * 32);
#pragma unroll
    for (int q = 0; q < 8; q++) {
        float4 v = hp[q];
        h[q * 4] = v.x; h[q * 4 + 1] = v.y; h[q * 4 + 2] = v.z; h[q * 4 + 3] = v.w;
    }
    float acc = bb[0];
#pragma unroll 4
    for (int j = 0; j < 64; j++) {
        float t = ab[j];
#pragma unroll
        for (int i = 0; i < 32; i++) t = fmaf(h[i], aw[i * 64 + j], t);
        acc = fmaf(fmaxf(t, 0.f), bw[j], acc);
    }
    out[n] = acc;
#pragma unroll
    for (int d = 0; d < 3; d++) {
        int idx = NN + n * 3 + d;
        if (idx < out_size) out[idx] = g_coord[n * 3 + d];
    }
}

// ---------------- launch ----------------
extern "C" void kernel_launch(void* const* d_in, const int* in_sizes, int n_in,
                              void* d_out, int out_size) {
    const float* x      = (const float*)d_in[0];
    const void*  ei     = d_in[1];
    const float* ea     = (const float*)d_in[2];
    const float* ci     = (const float*)d_in[3];
    const float* fc1w   = (const float*)d_in[4];
    const float* fc1b   = (const float*)d_in[5];
    const float* k1w    = (const float*)d_in[6];
    const float* k1b    = (const float*)d_in[7];
    const float* k2w    = (const float*)d_in[8];
    const float* k2b    = (const float*)d_in[9];
    const float* k3w    = (const float*)d_in[10];
    const float* k3b    = (const float*)d_in[11];
    const float* cm1w   = (const float*)d_in[12];
    const float* cm1b   = (const float*)d_in[13];
    const float* cm2w   = (const float*)d_in[14];
    const float* cm2b   = (const float*)d_in[15];
    const float* fc2aw  = (const float*)d_in[16];
    const float* fc2ab  = (const float*)d_in[17];
    const float* fc2bw  = (const float*)d_in[18];
    const float* fc2bb  = (const float*)d_in[19];
    float* out = (float*)d_out;

    cudaFuncSetAttribute(edge_kernel, cudaFuncAttributeMaxDynamicSharedMemorySize,
                         SMEM_EDGE_FLOATS * 4);
    cudaFuncSetAttribute(k2_mma_kernel, cudaFuncAttributeMaxDynamicSharedMemorySize,
                         K2_SMEM_FLOATS * 4);

    // Slot 4 = layer-0 G_mma (profiler capture window).
    detect_kernel<<<1, 32>>>(ei);
    zero_sort_kernel<<<(NN + 255) / 256, 256>>>();
    h0_kernel<<<(NN * 32 + 255) / 256, 256>>>(x, fc1w, fc1b);
    G_mma_kernel<<<dim3((NN + 63) / 64, 16), 256>>>(k3w);
    hist_kernel<<<(EE + 255) / 256, 256>>>(ei);
    scan_kernel<<<1, 1024>>>();
    cntf_kernel<<<(NN + 255) / 256, 256>>>();
    scatter_kernel<<<(EE + 255) / 256, 256>>>(ei);
    coordinit_kernel<<<(NN * 3 + 255) / 256, 256>>>(ci);
    w2split_kernel<<<128, 256>>>(k2w);
    k2_mma_kernel<<<EE / 32, 256, K2_SMEM_FLOATS * 4>>>(ea, k1w, k1b, k2b);

    for (int layer = 0; layer < 4; layer++) {
        if (layer > 0)
            G_mma_kernel<<<dim3((NN + 63) / 64, 16), 256>>>(k3w);
        bias_zero_kernel<<<(NN * 32 + 255) / 256, 256>>>(k3b);
        edge_kernel<<<NN / NPB, 256, SMEM_EDGE_FLOATS * 4>>>(ei, cm1w, cm1b, cm2w, cm2b);
        node_kernel<<<(NN * 32 + 255) / 256, 256>>>();
    }

    out_kernel<<<(NN + 255) / 256, 256>>>(fc2aw, fc2ab, fc2bw, fc2bb, out, out_size);
}

// round 14
// speedup vs baseline: 1.6334x; 1.2178x over previous
#include <cuda_runtime.h>

#define NN 10000
#define EE 300000
#define NPB 4   // nodes per edge-kernel block

// ---------------- scratch (__device__ globals, no allocs) ----------------
__device__ __align__(16) float g_h[NN * 32];
__device__ __align__(16) float g_k2[(size_t)EE * 256];
__device__ __align__(16) float g_G2[(size_t)NN * 8192];   // [n][c*32+i] node-major
__device__ __align__(16) float g_Bias[NN * 32];
__device__ __align__(16) float g_agg[NN * 32];
__device__ __align__(16) float g_cacc[NN * 3];
__device__ __align__(16) float g_coord[NN * 3];
__device__ __align__(16) float g_w2b[128 * 256];
__device__ __align__(16) float g_w2s[128 * 256];
__device__ __align__(16) float g_k3b[32 * 8192];   // [j][ci] tf32-big of ker3
__device__ __align__(16) float g_k3s[32 * 8192];   // [j][ci] tf32-small
__device__ float g_cntf[NN];
__device__ int   g_colcnt[NN];
__device__ int   g_rowcnt[NN];
__device__ int   g_cursor[NN];
__device__ int   g_colstart[NN + 1];
__device__ int   g_perm[EE];
__device__ int   g_is64;

// ---------------- tf32 / async helpers ----------------
__device__ __forceinline__ float tf32r(float f) {
    unsigned r;
    asm("cvt.rna.tf32.f32 %0, %1;" : "=r"(r) : "f"(f));
    return __uint_as_float(r);
}

__device__ __forceinline__ void mma_tf32(float* c, const unsigned* a, const unsigned* b) {
    asm volatile(
        "mma.sync.aligned.m16n8k8.row.col.f32.tf32.tf32.f32 "
        "{%0,%1,%2,%3}, {%4,%5,%6,%7}, {%8,%9}, {%0,%1,%2,%3};"
        : "+f"(c[0]), "+f"(c[1]), "+f"(c[2]), "+f"(c[3])
        : "r"(a[0]), "r"(a[1]), "r"(a[2]), "r"(a[3]), "r"(b[0]), "r"(b[1]));
}

__device__ __forceinline__ void cp_async16(void* smem_dst, const void* gmem_src) {
    unsigned s = (unsigned)__cvta_generic_to_shared(smem_dst);
    asm volatile("cp.async.cg.shared.global [%0], [%1], 16;\n" :: "r"(s), "l"(gmem_src));
}
#define CP_COMMIT() asm volatile("cp.async.commit_group;\n" ::)
#define CP_WAIT(N)  asm volatile("cp.async.wait_group %0;\n" :: "n"(N))

// ---------------- edge-index dtype handling ----------------
__global__ void detect_kernel(const void* __restrict__ ei) {
    const int* w = (const int*)ei;
    int lane = threadIdx.x;
    int hi = w[2 * lane + 1];
    unsigned any = __ballot_sync(0xffffffffu, hi != 0);
    if (lane == 0) g_is64 = (any == 0u) ? 1 : 0;
}

__device__ __forceinline__ int eidx(const void* __restrict__ ei, long long pos, int is64) {
    int v = is64 ? (int)((const long long*)ei)[pos] : ((const int*)ei)[pos];
    return min(max(v, 0), NN - 1);
}

// ---------------- small utility kernels ----------------
__global__ void zero_sort_kernel() {
    int i = blockIdx.x * blockDim.x + threadIdx.x;
    if (i < NN) { g_colcnt[i] = 0; g_rowcnt[i] = 0; g_cursor[i] = 0; }
}

__global__ void coordinit_kernel(const float* __restrict__ ci) {
    int i = blockIdx.x * blockDim.x + threadIdx.x;
    if (i < NN * 3) g_coord[i] = ci[i];
}

__global__ void hist_kernel(const void* __restrict__ ei) {
    int e = blockIdx.x * blockDim.x + threadIdx.x;
    int is64 = g_is64;
    if (e < EE) {
        atomicAdd(&g_rowcnt[eidx(ei, e, is64)], 1);
        atomicAdd(&g_colcnt[eidx(ei, (long long)EE + e, is64)], 1);
    }
}

__global__ void cntf_kernel() {
    int n = blockIdx.x * blockDim.x + threadIdx.x;
    if (n < NN) g_cntf[n] = fmaxf(1.f, (float)g_rowcnt[n]);
}

__global__ void scan_kernel() {
    const int BPT = 10;
    int t = threadIdx.x;
    int loc[BPT];
    int s = 0;
#pragma unroll
    for (int j = 0; j < BPT; j++) {
        int b = t * BPT + j;
        int v = (b < NN) ? g_colcnt[b] : 0;
        loc[j] = s; s += v;
    }
    unsigned full = 0xffffffffu;
    int lane = t & 31, wid = t >> 5;
    int v = s;
#pragma unroll
    for (int o = 1; o < 32; o <<= 1) {
        int u = __shfl_up_sync(full, v, o);
        if (lane >= o) v += u;
    }
    __shared__ int wsum[32];
    if (lane == 31) wsum[wid] = v;
    __syncthreads();
    if (wid == 0) {
        int x = wsum[lane];
#pragma unroll
        for (int o = 1; o < 32; o <<= 1) {
            int u = __shfl_up_sync(full, x, o);
            if (lane >= o) x += u;
        }
        wsum[lane] = x;
    }
    __syncthreads();
    int excl = v - s + (wid ? wsum[wid - 1] : 0);
#pragma unroll
    for (int j = 0; j < BPT; j++) {
        int b = t * BPT + j;
        if (b < NN) g_colstart[b] = excl + loc[j];
    }
    if (t == 1023) g_colstart[NN] = wsum[31];
}

__global__ void scatter_kernel(const void* __restrict__ ei) {
    int e = blockIdx.x * blockDim.x + threadIdx.x;
    if (e < EE) {
        int c = eidx(ei, (long long)EE + e, g_is64);
        int p = atomicAdd(&g_cursor[c], 1);
        g_perm[g_colstart[c] + p] = e;
    }
}

// ---------------- model kernels ----------------
__global__ void h0_kernel(const float* __restrict__ x,
                          const float* __restrict__ w, const float* __restrict__ b) {
    int idx = blockIdx.x * blockDim.x + threadIdx.x;
    if (idx >= NN * 32) return;
    int n = idx >> 5, i = idx & 31;
    float acc = b[i];
#pragma unroll
    for (int f = 0; f < 3; f++) acc = fmaf(x[n * 3 + f], w[f * 32 + i], acc);
    g_h[idx] = acc;
}

// Precompute tf32 splits of W2 once.
__global__ void w2split_kernel(const float* __restrict__ w2) {
    int i = blockIdx.x * blockDim.x + threadIdx.x;
    if (i < 128 * 256) {
        float v = w2[i];
        float b = tf32r(v);
        g_w2b[i] = b;
        g_w2s[i] = tf32r(v - b);
    }
}

// Precompute tf32 splits of ker3 once, in [j][ci] stage layout (layer-invariant).
__global__ void k3split_kernel(const float* __restrict__ k3w) {
    int i = blockIdx.x * blockDim.x + threadIdx.x;
    if (i >= 32 * 8192) return;
    int j = i >> 13, ci = i & 8191;
    float v = k3w[(size_t)(ci >> 5) * 1024 + (ci & 31) * 32 + j];
    float b = tf32r(v);
    g_k3b[(size_t)j * 8192 + ci] = b;
    g_k3s[(size_t)j * 8192 + ci] = tf32r(v - b);
}

// k2 v3: 32 edges x 256 cols per block; warp tile 32x32; K-chunks of 16.
#define K2_SMEM_FLOATS 14112
__global__ void __launch_bounds__(256) k2_mma_kernel(
    const float* __restrict__ ea,
    const float* __restrict__ w1, const float* __restrict__ b1,
    const float* __restrict__ b2)
{
    extern __shared__ float sk[];
    float* w2b_s = sk;            // 16*264
    float* w2s_s = sk + 4224;     // 16*264
    float* kt    = sk;            // 32*260 (reuses w2 region after MMA)
    float* As_b  = sk + 8448;     // 32*20
    float* As_s  = sk + 9088;     // 32*20
    float* t1f   = sk + 9728;     // 32*129
    float* b2s   = sk + 13856;    // 256

    int e0 = blockIdx.x * 32;
    int tid = threadIdx.x;

    if (tid < 256) b2s[tid] = b2[tid];
    for (int idx = tid; idx < 32 * 128; idx += 256) {
        int el = idx >> 7, j = idx & 127;
        float acc = b1[j];
#pragma unroll
        for (int f = 0; f < 6; f++) acc = fmaf(ea[(e0 + el) * 6 + f], w1[f * 128 + j], acc);
        t1f[el * 129 + j] = fmaxf(acc, 0.f);
    }

    int w = tid >> 5, lane = tid & 31;
    int g = lane >> 2, tig = lane & 3;
    int wn = w;

    float acc[2][4][4] = {};

#pragma unroll 1
    for (int kb = 0; kb < 8; kb++) {
        __syncthreads();
        for (int idx = tid; idx < 1024; idx += 256) {
            int r = idx >> 6, q = idx & 63;
            cp_async16(w2b_s + r * 264 + q * 4, g_w2b + (kb * 16 + r) * 256 + q * 4);
            cp_async16(w2s_s + r * 264 + q * 4, g_w2s + (kb * 16 + r) * 256 + q * 4);
        }
        CP_COMMIT();
        for (int idx = tid; idx < 512; idx += 256) {
            int el = idx >> 4, kl = idx & 15;
            float v = t1f[el * 129 + kb * 16 + kl];
            float b = tf32r(v);
            As_b[el * 20 + kl] = b;
            As_s[el * 20 + kl] = tf32r(v - b);
        }
        CP_WAIT(0);
        __syncthreads();

#pragma unroll
        for (int ks = 0; ks < 2; ks++) {
            int kk = ks * 8;
            unsigned ab[2][4], asr[2][4];
#pragma unroll
            for (int mi = 0; mi < 2; mi++) {
                int r0 = mi * 16;
                ab[mi][0]  = __float_as_uint(As_b[(r0 + g) * 20 + kk + tig]);
                ab[mi][1]  = __float_as_uint(As_b[(r0 + g + 8) * 20 + kk + tig]);
                ab[mi][2]  = __float_as_uint(As_b[(r0 + g) * 20 + kk + tig + 4]);
                ab[mi][3]  = __float_as_uint(As_b[(r0 + g + 8) * 20 + kk + tig + 4]);
                asr[mi][0] = __float_as_uint(As_s[(r0 + g) * 20 + kk + tig]);
                asr[mi][1] = __float_as_uint(As_s[(r0 + g + 8) * 20 + kk + tig]);
                asr[mi][2] = __float_as_uint(As_s[(r0 + g) * 20 + kk + tig + 4]);
                asr[mi][3] = __float_as_uint(As_s[(r0 + g + 8) * 20 + kk + tig + 4]);
            }
            unsigned bb[4][2], bsr[4][2];
#pragma unroll
            for (int ni = 0; ni < 4; ni++) {
                int c0l = wn * 32 + ni * 8 + g;
                bb[ni][0]  = __float_as_uint(w2b_s[(kk + tig) * 264 + c0l]);
                bb[ni][1]  = __float_as_uint(w2b_s[(kk + tig + 4) * 264 + c0l]);
                bsr[ni][0] = __float_as_uint(w2s_s[(kk + tig) * 264 + c0l]);
                bsr[ni][1] = __float_as_uint(w2s_s[(kk + tig + 4) * 264 + c0l]);
            }
#pragma unroll
            for (int mi = 0; mi < 2; mi++)
#pragma unroll
                for (int ni = 0; ni < 4; ni++) {
                    mma_tf32(acc[mi][ni], ab[mi], bb[ni]);
                    mma_tf32(acc[mi][ni], ab[mi], bsr[ni]);
                    mma_tf32(acc[mi][ni], asr[mi], bb[ni]);
                }
        }
    }

    __syncthreads();
#pragma unroll
    for (int mi = 0; mi < 2; mi++) {
        int r = mi * 16 + g;
#pragma unroll
        for (int ni = 0; ni < 4; ni++) {
            int col = wn * 32 + ni * 8 + 2 * tig;
            kt[r * 260 + col]           = acc[mi][ni][0];
            kt[r * 260 + col + 1]       = acc[mi][ni][1];
            kt[(r + 8) * 260 + col]     = acc[mi][ni][2];
            kt[(r + 8) * 260 + col + 1] = acc[mi][ni][3];
        }
    }
    __syncthreads();
    for (int idx = tid; idx < 8192; idx += 256) {
        int row = idx >> 8, col = idx & 255;
        float v = fmaxf(kt[row * 260 + col] + b2s[col], 0.f);
        g_k2[(size_t)(e0 + row) * 256 + col] = v;
    }
}

// G2 v2: bk splits cp.async'd from precomputed g_k3b/g_k3s (no cvt, no LDG round trip).
__global__ void __launch_bounds__(256) G_mma_kernel() {
    __shared__ float hs_b[64 * 36], hs_s[64 * 36];
    __shared__ float bk_b[32 * 72], bk_s[32 * 72];
    __shared__ float Gt[64 * 65];

    int nn0 = blockIdx.x * 64;
    int ciQ = blockIdx.y * 512;
    int tid = threadIdx.x;

    for (int idx = tid; idx < 64 * 32; idx += 256) {
        int nl = idx >> 5, j = idx & 31;
        int n = nn0 + nl;
        float v = (n < NN) ? g_h[n * 32 + j] : 0.f;
        float b = tf32r(v);
        hs_b[nl * 36 + j] = b;
        hs_s[nl * 36 + j] = tf32r(v - b);
    }

    int w = tid >> 5, lane = tid & 31;
    int g = lane >> 2, tig = lane & 3;
    int wm = w & 1, wn = w >> 1;

#pragma unroll 1
    for (int cq = 0; cq < 8; cq++) {
        int ci0 = ciQ + cq * 64;
        __syncthreads();    // hs visible (first); prior bk readers + Gt writers done
        for (int idx = tid; idx < 512; idx += 256) {
            int r = idx >> 4, q = idx & 15;
            cp_async16(bk_b + r * 72 + q * 4, g_k3b + (size_t)r * 8192 + ci0 + q * 4);
            cp_async16(bk_s + r * 72 + q * 4, g_k3s + (size_t)r * 8192 + ci0 + q * 4);
        }
        CP_COMMIT();
        CP_WAIT(0);
        __syncthreads();

        float acc[2][2][4] = {};
#pragma unroll
        for (int ks = 0; ks < 4; ks++) {
            int kk = ks * 8;
            unsigned ab[2][4], asr[2][4], bb[2][2], bsr[2][2];
#pragma unroll
            for (int mi = 0; mi < 2; mi++) {
                int r0 = wm * 32 + mi * 16 + g;
                ab[mi][0]  = __float_as_uint(hs_b[r0 * 36 + kk + tig]);
                ab[mi][1]  = __float_as_uint(hs_b[(r0 + 8) * 36 + kk + tig]);
                ab[mi][2]  = __float_as_uint(hs_b[r0 * 36 + kk + tig + 4]);
                ab[mi][3]  = __float_as_uint(hs_b[(r0 + 8) * 36 + kk + tig + 4]);
                asr[mi][0] = __float_as_uint(hs_s[r0 * 36 + kk + tig]);
                asr[mi][1] = __float_as_uint(hs_s[(r0 + 8) * 36 + kk + tig]);
                asr[mi][2] = __float_as_uint(hs_s[r0 * 36 + kk + tig + 4]);
                asr[mi][3] = __float_as_uint(hs_s[(r0 + 8) * 36 + kk + tig + 4]);
            }
#pragma unroll
            for (int ni = 0; ni < 2; ni++) {
                int c0l = wn * 16 + ni * 8 + g;
                bb[ni][0]  = __float_as_uint(bk_b[(kk + tig) * 72 + c0l]);
                bb[ni][1]  = __float_as_uint(bk_b[(kk + tig + 4) * 72 + c0l]);
                bsr[ni][0] = __float_as_uint(bk_s[(kk + tig) * 72 + c0l]);
                bsr[ni][1] = __float_as_uint(bk_s[(kk + tig + 4) * 72 + c0l]);
            }
#pragma unroll
            for (int mi = 0; mi < 2; mi++)
#pragma unroll
                for (int ni = 0; ni < 2; ni++) {
                    mma_tf32(acc[mi][ni], ab[mi], bb[ni]);
                    mma_tf32(acc[mi][ni], ab[mi], bsr[ni]);
                    mma_tf32(acc[mi][ni], asr[mi], bb[ni]);
                }
        }

#pragma unroll
        for (int mi = 0; mi < 2; mi++) {
            int rl = wm * 32 + mi * 16 + g;
#pragma unroll
            for (int ni = 0; ni < 2; ni++) {
                int cl = wn * 16 + ni * 8 + 2 * tig;
                Gt[rl * 65 + cl]           = acc[mi][ni][0];
                Gt[rl * 65 + cl + 1]       = acc[mi][ni][1];
                Gt[(rl + 8) * 65 + cl]     = acc[mi][ni][2];
                Gt[(rl + 8) * 65 + cl + 1] = acc[mi][ni][3];
            }
        }
        __syncthreads();
        for (int idx = tid; idx < 4096; idx += 256) {
            int row = idx >> 6, col = idx & 63;
            int n = nn0 + row;
            if (n < NN) g_G2[(size_t)n * 8192 + ci0 + col] = Gt[row * 65 + col];
        }
    }
}

// Bias[n][i] = sum_j ker3_b[i*32+j] * h[n][j] (exact fp32); zero agg/cacc.
__global__ void bias_zero_kernel(const float* __restrict__ b3) {
    int idx = blockIdx.x * blockDim.x + threadIdx.x;
    if (idx < NN * 3) g_cacc[idx] = 0.f;
    if (idx >= NN * 32) return;
    int n = idx >> 5, i = idx & 31;
    float acc = 0.f;
#pragma unroll
    for (int j = 0; j < 32; j++) acc = fmaf(b3[i * 32 + j], g_h[n * 32 + j], acc);
    g_Bias[idx] = acc;
    g_agg[idx] = 0.f;
}

// Edge kernel v4: single G buffer (75.5KB smem -> 3 blocks/SM). G2 cp.async
// issued first, k2/es staged while in flight, wait only before compute.
#define SMEM_EDGE_FLOATS 18884
__global__ void __launch_bounds__(256) edge_kernel(
    const void* __restrict__ ei,
    const float* __restrict__ cm1w, const float* __restrict__ cm1b,
    const float* __restrict__ cm2w, const float* __restrict__ cm2b)
{
    extern __shared__ float sm[];
    float* Gs    = sm;                  // 8192
    float* k2s   = sm + 8192;           // 32*260 = 8320
    float* cm1s  = sm + 16512;          // 32*33 = 1056
    float* ms_   = sm + 17568;          // 32*36 = 1152
    float* Bs    = sm + 18720;          // 32
    float* cm1bs = sm + 18752;          // 32
    float* cm2s  = sm + 18784;          // 32
    int*   es    = (int*)(sm + 18816);  // 32
    int*   rs    = (int*)(sm + 18848);  // 32
    float* ccolp = sm + 18880;          // [0..2]=ccol, [3]=cm2b0

    int tid = threadIdx.x, w = tid >> 5, lane = tid & 31;
    int is64 = g_is64;
    int n0 = blockIdx.x * NPB;

    for (int idx = tid; idx < 1024; idx += 256)
        cm1s[(idx >> 5) * 33 + (idx & 31)] = cm1w[idx];
    if (tid < 32) { cm1bs[tid] = cm1b[tid]; cm2s[tid] = cm2w[tid]; }
    if (tid == 0) ccolp[3] = cm2b[0];

    int lg = lane >> 3;
    int iq = lane & 7;
    const unsigned full = 0xffffffffu;

#pragma unroll 1
    for (int t = 0; t < NPB; t++) {
        int n = n0 + t;
        // issue async G2 load for this node (prior node fully done via end sync)
        {
            const float* src = g_G2 + (size_t)n * 8192;
            for (int idx = tid; idx < 2048; idx += 256)
                cp_async16(Gs + idx * 4, src + idx * 4);
            CP_COMMIT();
        }
        if (tid < 32) Bs[tid] = g_Bias[n * 32 + tid];
        if (tid < 3) ccolp[tid] = g_coord[n * 3 + tid];

        int cs0 = g_colstart[n];
        int deg = g_colstart[n + 1] - cs0;

        for (int base = 0; base < deg; base += 32) {
            if (base) __syncthreads();     // prior group's readers done
            if (tid < 32) {
                int p = base + tid;
                int e = (p < deg) ? g_perm[cs0 + p] : -1;
                es[tid] = e;
                rs[tid] = (e >= 0) ? eidx(ei, e, is64) : 0;
            }
            __syncthreads();
            // stage k2 rows (overlaps with G2 cp.async on first group)
            for (int idx = tid; idx < 2048; idx += 256) {
                int el = idx >> 6, c4 = idx & 63;
                int e = es[el];
                float4 v = (e >= 0) ? ((const float4*)g_k2)[(size_t)e * 64 + c4]
                                    : make_float4(0.f, 0.f, 0.f, 0.f);
                *(float4*)&k2s[el * 260 + c4 * 4] = v;
            }
            if (base == 0) CP_WAIT(0);     // G2 resident from here on
            __syncthreads();

            int e_l0 = w * 4;
            float acc[4][4] = {};
            const float4* G4 = (const float4*)Gs;
#pragma unroll 4
            for (int cb = 0; cb < 64; cb++) {
                int c = cb * 4 + lg;
                float4 gv = G4[c * 8 + iq];
                float k0 = k2s[(e_l0 + 0) * 260 + c];
                float k1 = k2s[(e_l0 + 1) * 260 + c];
                float k2v = k2s[(e_l0 + 2) * 260 + c];
                float k3 = k2s[(e_l0 + 3) * 260 + c];
                acc[0][0] = fmaf(k0, gv.x, acc[0][0]); acc[0][1] = fmaf(k0, gv.y, acc[0][1]);
                acc[0][2] = fmaf(k0, gv.z, acc[0][2]); acc[0][3] = fmaf(k0, gv.w, acc[0][3]);
                acc[1][0] = fmaf(k1, gv.x, acc[1][0]); acc[1][1] = fmaf(k1, gv.y, acc[1][1]);
                acc[1][2] = fmaf(k1, gv.z, acc[1][2]); acc[1][3] = fmaf(k1, gv.w, acc[1][3]);
                acc[2][0] = fmaf(k2v, gv.x, acc[2][0]); acc[2][1] = fmaf(k2v, gv.y, acc[2][1]);
                acc[2][2] = fmaf(k2v, gv.z, acc[2][2]); acc[2][3] = fmaf(k2v, gv.w, acc[2][3]);
                acc[3][0] = fmaf(k3, gv.x, acc[3][0]); acc[3][1] = fmaf(k3, gv.y, acc[3][1]);
                acc[3][2] = fmaf(k3, gv.z, acc[3][2]); acc[3][3] = fmaf(k3, gv.w, acc[3][3]);
            }
#pragma unroll
            for (int q = 0; q < 4; q++)
#pragma unroll
                for (int c = 0; c < 4; c++) {
                    acc[q][c] += __shfl_xor_sync(full, acc[q][c], 8);
                    acc[q][c] += __shfl_xor_sync(full, acc[q][c], 16);
                }
            if (lane < 8) {
#pragma unroll
                for (int q = 0; q < 4; q++)
                    *(float4*)&ms_[(e_l0 + q) * 36 + iq * 4] =
                        make_float4(acc[q][0], acc[q][1], acc[q][2], acc[q][3]);
            }
            __syncwarp();
#pragma unroll
            for (int q = 0; q < 4; q++) {
                int el = e_l0 + q;
                float mf = ms_[el * 36 + lane] + Bs[lane];
                ms_[el * 36 + lane] = mf;
                if (es[el] >= 0) atomicAdd(&g_agg[rs[el] * 32 + lane], mf);
            }
            __syncwarp();
#pragma unroll 1
            for (int q = 0; q < 4; q++) {
                int el = e_l0 + q;
                float tt = cm1bs[lane];
#pragma unroll
                for (int i = 0; i < 32; i++)
                    tt = fmaf(ms_[el * 36 + i], cm1s[i * 33 + lane], tt);
                tt = fmaxf(tt, 0.f) * cm2s[lane];
#pragma unroll
                for (int off = 16; off; off >>= 1) tt += __shfl_xor_sync(full, tt, off);
                int e = es[el];
                if (e >= 0 && lane < 3) {
                    float we = tt + ccolp[3];
                    int r = rs[el];
                    atomicAdd(&g_cacc[r * 3 + lane], (g_coord[r * 3 + lane] - ccolp[lane]) * we);
                }
            }
        }
        __syncthreads();   // all reads of Gs/Bs/ccol done before next node's loads
    }
}

__global__ void node_kernel() {
    int idx = blockIdx.x * blockDim.x + threadIdx.x;
    if (idx >= NN * 32) return;
    int n = idx >> 5, i = idx & 31;
    float cf = g_cntf[n];
    float hv = g_h[idx] + g_agg[idx] / cf;
    g_h[idx] = fmaxf(hv, 0.f);
    if (i < 3) g_coord[n * 3 + i] += g_cacc[n * 3 + i] / cf;
}

__global__ void out_kernel(const float* __restrict__ aw, const float* __restrict__ ab,
                           const float* __restrict__ bw, const float* __restrict__ bb,
                           float* __restrict__ out, int out_size) {
    int n = blockIdx.x * blockDim.x + threadIdx.x;
    if (n >= NN) return;
    float h[32];
    const float4* hp = (const float4*)(g_h + n * 32);
#pragma unroll
    for (int q = 0; q < 8; q++) {
        float4 v = hp[q];
        h[q * 4] = v.x; h[q * 4 + 1] = v.y; h[q * 4 + 2] = v.z; h[q * 4 + 3] = v.w;
    }
    float acc = bb[0];
#pragma unroll 4
    for (int j = 0; j < 64; j++) {
        float t = ab[j];
#pragma unroll
        for (int i = 0; i < 32; i++) t = fmaf(h[i], aw[i * 64 + j], t);
        acc = fmaf(fmaxf(t, 0.f), bw[j], acc);
    }
    out[n] = acc;
#pragma unroll
    for (int d = 0; d < 3; d++) {
        int idx = NN + n * 3 + d;
        if (idx < out_size) out[idx] = g_coord[n * 3 + d];
    }
}

// ---------------- launch ----------------
extern "C" void kernel_launch(void* const* d_in, const int* in_sizes, int n_in,
                              void* d_out, int out_size) {
    const float* x      = (const float*)d_in[0];
    const void*  ei     = d_in[1];
    const float* ea     = (const float*)d_in[2];
    const float* ci     = (const float*)d_in[3];
    const float* fc1w   = (const float*)d_in[4];
    const float* fc1b   = (const float*)d_in[5];
    const float* k1w    = (const float*)d_in[6];
    const float* k1b    = (const float*)d_in[7];
    const float* k2w    = (const float*)d_in[8];
    const float* k2b    = (const float*)d_in[9];
    const float* k3w    = (const float*)d_in[10];
    const float* k3b    = (const float*)d_in[11];
    const float* cm1w   = (const float*)d_in[12];
    const float* cm1b   = (const float*)d_in[13];
    const float* cm2w   = (const float*)d_in[14];
    const float* cm2b   = (const float*)d_in[15];
    const float* fc2aw  = (const float*)d_in[16];
    const float* fc2ab  = (const float*)d_in[17];
    const float* fc2bw  = (const float*)d_in[18];
    const float* fc2bb  = (const float*)d_in[19];
    float* out = (float*)d_out;

    cudaFuncSetAttribute(edge_kernel, cudaFuncAttributeMaxDynamicSharedMemorySize,
                         SMEM_EDGE_FLOATS * 4);
    cudaFuncSetAttribute(k2_mma_kernel, cudaFuncAttributeMaxDynamicSharedMemorySize,
                         K2_SMEM_FLOATS * 4);

    // Slot 4 = k2_mma (profiler capture window) — verify v3 roofline.
    detect_kernel<<<1, 32>>>(ei);
    zero_sort_kernel<<<(NN + 255) / 256, 256>>>();
    w2split_kernel<<<128, 256>>>(k2w);
    k2_mma_kernel<<<EE / 32, 256, K2_SMEM_FLOATS * 4>>>(ea, k1w, k1b, k2b);
    hist_kernel<<<(EE + 255) / 256, 256>>>(ei);
    scan_kernel<<<1, 1024>>>();
    cntf_kernel<<<(NN + 255) / 256, 256>>>();
    scatter_kernel<<<(EE + 255) / 256, 256>>>(ei);
    coordinit_kernel<<<(NN * 3 + 255) / 256, 256>>>(ci);
    h0_kernel<<<(NN * 32 + 255) / 256, 256>>>(x, fc1w, fc1b);
    k3split_kernel<<<(32 * 8192 + 255) / 256, 256>>>(k3w);

    for (int layer = 0; layer < 4; layer++) {
        G_mma_kernel<<<dim3((NN + 63) / 64, 16), 256>>>();
        bias_zero_kernel<<<(NN * 32 + 255) / 256, 256>>>(k3b);
        edge_kernel<<<NN / NPB, 256, SMEM_EDGE_FLOATS * 4>>>(ei, cm1w, cm1b, cm2w, cm2b);
        node_kernel<<<(NN * 32 + 255) / 256, 256>>>();
    }

    out_kernel<<<(NN + 255) / 256, 256>>>(fc2aw, fc2ab, fc2bw, fc2bb, out, out_size);
}